// round 12
// baseline (speedup 1.0000x reference)
#include <cuda_runtime.h>
#include <cuda_fp16.h>
#include <math.h>
#include <stdint.h>

#define NB 8
#define NC 256
#define NTOK 16384

__device__ __forceinline__ uint32_t s2u(const void* p) {
    uint32_t a;
    asm("{ .reg .u64 t; cvta.to.shared.u64 t, %1; cvt.u32.u64 %0, t; }" : "=r"(a) : "l"(p));
    return a;
}
__device__ __forceinline__ void ldm_x4(uint32_t r[4], uint32_t addr) {
    asm volatile("ldmatrix.sync.aligned.m8n8.x4.shared.b16 {%0,%1,%2,%3}, [%4];"
        : "=r"(r[0]), "=r"(r[1]), "=r"(r[2]), "=r"(r[3]) : "r"(addr));
}
__device__ __forceinline__ void mma_f16(float c[4], const uint32_t a[4], const uint32_t b[2]) {
    asm volatile("mma.sync.aligned.m16n8k16.row.col.f32.f16.f16.f32 "
        "{%0,%1,%2,%3}, {%4,%5,%6,%7}, {%8,%9}, {%0,%1,%2,%3};"
        : "+f"(c[0]), "+f"(c[1]), "+f"(c[2]), "+f"(c[3])
        : "r"(a[0]), "r"(a[1]), "r"(a[2]), "r"(a[3]), "r"(b[0]), "r"(b[1]));
}
__device__ __forceinline__ void cpa16(uint32_t s, const void* g) {
    asm volatile("cp.async.cg.shared.global [%0], [%1], 16;"
        :: "r"(s), "l"(__cvta_generic_to_global(g)));
}
#define CP_COMMIT() asm volatile("cp.async.commit_group;" ::: "memory")
#define CP_WAIT0() asm volatile("cp.async.wait_group 0;" ::: "memory")
#define CP_WAIT1() asm volatile("cp.async.wait_group 1;" ::: "memory")
#define BAR_SYNC(id) asm volatile("bar.sync %0, 128;" :: "r"(id) : "memory")

// ---------------- device scratch ----------------
__device__ float g_T[128 * 128];
__device__ float g_WkT[NC * NC];
__device__ float g_RK[128 * NC];
__device__ float g_PK[128 * NC];
__device__ float g_spart[(size_t)NB * 128 * 8192];
__device__ float g_S[NB * 8192];
__device__ float g_M[NB * NC * NC];          // transposed [co][ci]
__device__ float g_biasq[NB * NC];
__device__ float g_RQ[NB * 128 * NC];
__device__ float g_PQ[NB * 128 * NC];
__device__ __align__(16) __half g_Bw[2][256][264];      // Wk, Wv fp16 [co][ci]
__device__ __align__(16) __half g_Bm[NB][256][264];     // M fp16 [co][ci]

// t1 smem (bytes): A@0 67584 | B@67584 67584 (K rows0-63, V rows64-127) | KT@135168 | VT@152576
#define T1_B   67584
#define KT_OFF 135168
#define VT_OFF 152576
#define T1_TOT 169984
// t3 smem: A@0 67584 | B0@67584 | B1@135168 | mus@202752 | rss@203264
#define T3_B0  67584
#define T3_B1  135168
#define T3_MU  202752
#define T3_RS  203264
#define T3_TOT 203776

// ---------------- preps ----------------
__global__ void prep0_kernel(const float* __restrict__ Wk, const float* __restrict__ Wv) {
    int idx = blockIdx.x * 256 + threadIdx.x;
    int co = idx >> 8, ci = idx & 255;
    g_WkT[ci * NC + co] = Wk[idx];
    g_Bw[0][co][ci] = __float2half_rn(Wk[idx]);
    g_Bw[1][co][ci] = __float2half_rn(Wv[idx]);
    if (idx < 128 * 128) {
        int p = idx >> 7, c = idx & 127, j = c >> 1;
        float dimt = powf(10000.0f, (float)j * (1.0f / 64.0f));
        float t = (float)(p + 1) * (6.283185307179586f / (128.0f + 1e-6f)) / dimt;
        g_T[idx] = (c & 1) ? cosf(t) : sinf(t);
    }
}

__global__ void prep1_kernel() {
    int table = blockIdx.x >> 3, chunk = blockIdx.x & 7;
    int n = chunk * 32 + (threadIdx.x & 31);
    int yg = threadIdx.x >> 5;
    float acc[16];
#pragma unroll
    for (int i = 0; i < 16; i++) acc[i] = 0.f;
    const float* W = g_WkT + (table ? 128 * NC : 0);
#pragma unroll 4
    for (int c = 0; c < 128; c++) {
        float w = W[c * NC + n];
#pragma unroll
        for (int yy = 0; yy < 16; yy++) acc[yy] += g_T[(yg * 16 + yy) * 128 + c] * w;
    }
    float* dst = table ? g_PK : g_RK;
#pragma unroll
    for (int yy = 0; yy < 16; yy++) dst[(yg * 16 + yy) * NC + n] = acc[yy];
}

// x[ci][tok] -> A[tok 128][ci 256 pad 264] fp16 (256 threads)
__device__ __forceinline__ void load_x_tile(char* smem, const float* __restrict__ xb, int tid) {
    int tok = tid & 127, cig = tid >> 7;
#pragma unroll 1
    for (int p = 0; p < 16; p++) {
        int ci0 = (cig + p * 2) * 8;
        __half hv[8];
#pragma unroll
        for (int j = 0; j < 8; j++)
            hv[j] = __float2half_rn(xb[(size_t)(ci0 + j) * NTOK + tok]);
        *(uint4*)(smem + tok * 528 + ci0 * 2) = *(uint4*)hv;
    }
}

// ---------------- T1: fp16 K/V proj (m32n64 warps, op-split) + LN + fp16 scores ----------------
__global__ void __launch_bounds__(256, 1) t1_kernel(
    const float* __restrict__ x,
    const float* __restrict__ bk, const float* __restrict__ bv,
    const float* __restrict__ gK, const float* __restrict__ bKp,
    const float* __restrict__ gV, const float* __restrict__ bVp)
{
    extern __shared__ char smem[];
    const int tid = threadIdx.x, w = tid >> 5, lane = tid & 31;
    const int rb = blockIdx.x, b = blockIdx.y;
    const int n0 = rb * 128;
    uint32_t sb = s2u(smem);

    const int op = w >> 2, mt = w & 3;      // warp: m32 tile mt, operand op
    const uint32_t aH0 = sb + (mt * 32 + (lane & 15)) * 528 + ((lane & 16) ? 16 : 0);
    const int blrow = (lane & 7) + ((lane & 16) ? 8 : 0);
    const int blcol2 = (lane & 8) ? 16 : 0;
    const uint32_t bbase = sb + T1_B + (op * 64 + blrow) * 528 + blcol2;

    load_x_tile(smem, x + ((size_t)b * NC) * NTOK + n0, tid);
    __syncthreads();

#pragma unroll 1
    for (int nc = 0; nc < 4; nc++) {
        // group-split B load: K threads load K rows, V threads load V rows
        if (tid < 128) {
            for (int i = tid; i < 2112; i += 128)
                cpa16(sb + T1_B + i * 16, ((const uint4*)&g_Bw[0][nc * 64][0]) + i);
        } else {
            for (int i = tid - 128; i < 2112; i += 128)
                cpa16(sb + T1_B + 33792 + i * 16, ((const uint4*)&g_Bw[1][nc * 64][0]) + i);
        }
        CP_COMMIT(); CP_WAIT0();
        BAR_SYNC(1 + op);

        float acc[2][8][4];
#pragma unroll
        for (int t = 0; t < 2; t++)
#pragma unroll
            for (int f = 0; f < 8; f++)
#pragma unroll
                for (int j = 0; j < 4; j++) acc[t][f][j] = 0.f;

#pragma unroll 4
        for (int k = 0; k < 16; k++) {
            uint32_t a0[4], a1[4];
            ldm_x4(a0, aH0 + k * 32);
            ldm_x4(a1, aH0 + 16 * 528 + k * 32);
#pragma unroll
            for (int q = 0; q < 4; q++) {
                uint32_t bb[4];
                ldm_x4(bb, bbase + q * 16 * 528 + k * 32);
                mma_f16(acc[0][q * 2], a0, bb);
                mma_f16(acc[0][q * 2 + 1], a0, bb + 2);
                mma_f16(acc[1][q * 2], a1, bb);
                mma_f16(acc[1][q * 2 + 1], a1, bb + 2);
            }
        }

        // epilogue: +pos/bias -> per-head register LN -> transposed fp16 store
        {
            const int r0 = lane >> 2, cq = (lane & 3) * 2;
            float v[2][2][16];
            if (op == 0) {
#pragma unroll
                for (int t = 0; t < 2; t++)
#pragma unroll
                    for (int rh = 0; rh < 2; rh++) {
                        int row = mt * 32 + t * 16 + rh * 8 + r0;
#pragma unroll
                        for (int f = 0; f < 8; f++) {
                            int co = nc * 64 + f * 8 + cq;
                            float2 rk = *(const float2*)&g_RK[rb * NC + co];
                            float2 bkk = *(const float2*)&bk[co];
                            float2 pa = *(const float2*)&g_PK[row * NC + co];
                            v[t][rh][f * 2] = acc[t][f][rh * 2] + rk.x + pa.x + bkk.x;
                            v[t][rh][f * 2 + 1] = acc[t][f][rh * 2 + 1] + rk.y + pa.y + bkk.y;
                        }
                    }
            } else {
#pragma unroll
                for (int t = 0; t < 2; t++)
#pragma unroll
                    for (int rh = 0; rh < 2; rh++)
#pragma unroll
                        for (int f = 0; f < 8; f++) {
                            int co = nc * 64 + f * 8 + cq;
                            float2 bv2 = *(const float2*)&bv[co];
                            v[t][rh][f * 2] = acc[t][f][rh * 2] + bv2.x;
                            v[t][rh][f * 2 + 1] = acc[t][f][rh * 2 + 1] + bv2.y;
                        }
            }
            const float* gg = op ? gV : gK;
            const float* be = op ? bVp : bKp;
            float gv0[8], bv0[8], gv1[8], bv1[8];
#pragma unroll
            for (int f = 0; f < 4; f++)
#pragma unroll
                for (int j = 0; j < 2; j++) {
                    int d = f * 8 + cq + j;
                    gv0[f * 2 + j] = gg[(nc * 2) * 32 + d];
                    bv0[f * 2 + j] = be[(nc * 2) * 32 + d];
                    gv1[f * 2 + j] = gg[(nc * 2 + 1) * 32 + d];
                    bv1[f * 2 + j] = be[(nc * 2 + 1) * 32 + d];
                }
            uint32_t base = sb + (op ? VT_OFF : KT_OFF);
#pragma unroll
            for (int t = 0; t < 2; t++)
#pragma unroll
                for (int rh = 0; rh < 2; rh++) {
                    int row = mt * 32 + t * 16 + rh * 8 + r0;
                    float s0 = 0.f, q0 = 0.f, s1 = 0.f, q1 = 0.f;
#pragma unroll
                    for (int i = 0; i < 8; i++) {
                        float a = v[t][rh][i], c = v[t][rh][8 + i];
                        s0 += a; q0 += a * a; s1 += c; q1 += c * c;
                    }
#pragma unroll
                    for (int off = 1; off < 4; off <<= 1) {
                        s0 += __shfl_xor_sync(0xffffffffu, s0, off);
                        q0 += __shfl_xor_sync(0xffffffffu, q0, off);
                        s1 += __shfl_xor_sync(0xffffffffu, s1, off);
                        q1 += __shfl_xor_sync(0xffffffffu, q1, off);
                    }
                    float mu0 = s0 * (1.f / 32.f);
                    float rs0 = rsqrtf(q0 * (1.f / 32.f) - mu0 * mu0 + 1e-5f);
                    float mu1 = s1 * (1.f / 32.f);
                    float rs1 = rsqrtf(q1 * (1.f / 32.f) - mu1 * mu1 + 1e-5f);
#pragma unroll
                    for (int f = 0; f < 4; f++)
#pragma unroll
                        for (int j = 0; j < 2; j++) {
                            int d = f * 8 + cq + j;
                            __half h0 = __float2half_rn((v[t][rh][f * 2 + j] - mu0) * rs0 * gv0[f * 2 + j] + bv0[f * 2 + j]);
                            __half h1 = __float2half_rn((v[t][rh][8 + f * 2 + j] - mu1) * rs1 * gv1[f * 2 + j] + bv1[f * 2 + j]);
                            asm volatile("st.shared.u16 [%0], %1;" :: "r"(base + (uint32_t)d * 272 + row * 2), "h"(*(unsigned short*)&h0));
                            asm volatile("st.shared.u16 [%0], %1;" :: "r"(base + (uint32_t)(32 + d) * 272 + row * 2), "h"(*(unsigned short*)&h1));
                        }
                }
        }
        __syncthreads();

        // scores: S_h[d][e] = sum_{tok 128} K[tok][d] V[tok][e]
        {
            const int hl = w >> 2, dt = (w >> 1) & 1, et = w & 1;
            const uint32_t aB = sb + KT_OFF + (hl * 32 + dt * 16 + (lane & 15)) * 272
                              + ((lane & 16) ? 16 : 0);
            const uint32_t bB = sb + VT_OFF + (hl * 32 + et * 16 + blrow) * 272 + blcol2;
            float sc[2][4];
#pragma unroll
            for (int q = 0; q < 2; q++)
#pragma unroll
                for (int j = 0; j < 4; j++) sc[q][j] = 0.f;
#pragma unroll
            for (int k = 0; k < 8; k++) {
                uint32_t a[4], bb[4];
                ldm_x4(a, aB + k * 32);
                ldm_x4(bb, bB + k * 32);
                mma_f16(sc[0], a, bb);
                mma_f16(sc[1], a, bb + 2);
            }
            float* dst = g_spart + ((size_t)(b * 128 + rb)) * 8192 + (nc * 2 + hl) * 1024;
            int d0 = dt * 16 + (lane >> 2);
#pragma unroll
            for (int q = 0; q < 2; q++) {
                int e0 = et * 16 + q * 8 + (lane & 3) * 2;
                dst[d0 * 32 + e0] = sc[q][0];
                dst[d0 * 32 + e0 + 1] = sc[q][1];
                dst[(d0 + 8) * 32 + e0] = sc[q][2];
                dst[(d0 + 8) * 32 + e0 + 1] = sc[q][3];
            }
        }
        __syncthreads();
    }
}

// ---------------- k2 chain ----------------
__global__ void k2_reduce() {
    int b = blockIdx.x >> 5, seg = blockIdx.x & 31;
    int base = seg * 256 + threadIdx.x;
    float s = 0.f;
#pragma unroll 8
    for (int rb = 0; rb < 128; rb++) s += g_spart[((size_t)(b * 128 + rb)) * 8192 + base];
    g_S[b * 8192 + base] = s * (1.0f / 16384.0f);
}

__global__ void k2b_buildM(const float* __restrict__ Wq, const float* __restrict__ bq) {
    __shared__ float Wqs[256 * 33];
    int chunk = blockIdx.x, b = blockIdx.y;
    int co = threadIdx.x, h = co >> 5, e = co & 31;
    for (int idx = threadIdx.x; idx < 8192; idx += 256) {
        int row = idx >> 5, cil = idx & 31;
        Wqs[row * 33 + cil] = Wq[row * NC + chunk * 32 + cil];
    }
    float Scol[32];
#pragma unroll
    for (int d = 0; d < 32; d++) Scol[d] = g_S[b * 8192 + h * 1024 + d * 32 + e];
    __syncthreads();
    for (int cil = 0; cil < 32; cil++) {
        float m = 0.f;
#pragma unroll
        for (int d = 0; d < 32; d++) m += Wqs[(h * 32 + d) * 33 + cil] * Scol[d];
        g_M[(size_t)b * 65536 + (size_t)co * NC + chunk * 32 + cil] = m;
        g_Bm[b][co][chunk * 32 + cil] = __float2half_rn(m);
    }
    if (chunk == 0) {
        float bb = 0.f;
#pragma unroll
        for (int d = 0; d < 32; d++) bb += bq[h * 32 + d] * Scol[d];
        g_biasq[b * NC + co] = bb;
    }
}

__global__ void k2c_rqpq() {
    __shared__ float Ts[128];
    int p = blockIdx.x, b = blockIdx.y;
    int co = threadIdx.x;
    if (co < 128) Ts[co] = g_T[p * 128 + co];
    __syncthreads();
    const float4* Mr = (const float4*)(g_M + (size_t)b * 65536 + (size_t)co * NC);
    float accR = 0.f, accP = 0.f;
#pragma unroll 8
    for (int c4 = 0; c4 < 32; c4++) {
        float4 m0 = Mr[c4], m1 = Mr[32 + c4];
        float4 t4 = *(const float4*)&Ts[c4 * 4];
        accR += t4.x * m0.x + t4.y * m0.y + t4.z * m0.z + t4.w * m0.w;
        accP += t4.x * m1.x + t4.y * m1.y + t4.z * m1.z + t4.w * m1.w;
    }
    g_RQ[(b * 128 + p) * NC + co] = accR;
    g_PQ[(b * 128 + p) * NC + co] = accP;
}

// ---------------- T3: fp16 out GEMM (m32n64 warps, 2 double-buffered stages) ----------------
__global__ void __launch_bounds__(256, 1) t3_kernel(
    const float* __restrict__ x,
    const float* __restrict__ g_ln, const float* __restrict__ b_ln,
    float* __restrict__ out)
{
    extern __shared__ char smem[];
    const int tid = threadIdx.x, w = tid >> 5, lane = tid & 31;
    const int rb = blockIdx.x, b = blockIdx.y;
    const int n0 = rb * 128;
    uint32_t sb = s2u(smem);

    const int ch = w >> 2, mt = w & 3;      // warp: m32 tile mt, n64 chunk ch
    const uint32_t aH0 = sb + (mt * 32 + (lane & 15)) * 528 + ((lane & 16) ? 16 : 0);
    const int blrow = (lane & 7) + ((lane & 16) ? 8 : 0);
    const int blcol2 = (lane & 8) ? 16 : 0;

    for (int i = tid; i < 4224; i += 256)
        cpa16(sb + T3_B0 + i * 16, ((const uint4*)&g_Bm[b][0][0]) + i);
    CP_COMMIT();
    load_x_tile(smem, x + ((size_t)b * NC) * NTOK + n0, tid);
    for (int i = tid; i < 4224; i += 256)
        cpa16(sb + T3_B1 + i * 16, ((const uint4*)&g_Bm[b][128][0]) + i);
    CP_COMMIT();

    float acc[2][2][8][4];
#pragma unroll 1
    for (int s = 0; s < 2; s++) {
        if (s == 0) CP_WAIT1(); else CP_WAIT0();
        __syncthreads();
#pragma unroll
        for (int t = 0; t < 2; t++)
#pragma unroll
            for (int f = 0; f < 8; f++)
#pragma unroll
                for (int j = 0; j < 4; j++) acc[s][t][f][j] = 0.f;

        const uint32_t bbase = sb + (s ? T3_B1 : T3_B0) + (ch * 64 + blrow) * 528 + blcol2;
#pragma unroll 4
        for (int k = 0; k < 16; k++) {
            uint32_t a0[4], a1[4];
            ldm_x4(a0, aH0 + k * 32);
            ldm_x4(a1, aH0 + 16 * 528 + k * 32);
#pragma unroll
            for (int q = 0; q < 4; q++) {
                uint32_t bb[4];
                ldm_x4(bb, bbase + q * 16 * 528 + k * 32);
                mma_f16(acc[s][0][q * 2], a0, bb);
                mma_f16(acc[s][0][q * 2 + 1], a0, bb + 2);
                mma_f16(acc[s][1][q * 2], a1, bb);
                mma_f16(acc[s][1][q * 2 + 1], a1, bb + 2);
            }
        }
    }
    __syncthreads();

    float* stg = (float*)smem;          // [128][264] overlays A+B0
    float* mus = (float*)(smem + T3_MU);
    float* rss = (float*)(smem + T3_RS);
    {
        int r0 = lane >> 2, cq = (lane & 3) * 2;
#pragma unroll
        for (int s = 0; s < 2; s++)
#pragma unroll
            for (int t = 0; t < 2; t++)
#pragma unroll
                for (int rh = 0; rh < 2; rh++) {
                    int row = mt * 32 + t * 16 + rh * 8 + r0;
#pragma unroll
                    for (int f = 0; f < 8; f++) {
                        int co = s * 128 + ch * 64 + f * 8 + cq;
                        float2 rq = *(const float2*)&g_RQ[(b * 128 + rb) * NC + co];
                        float2 qb = *(const float2*)&g_biasq[b * NC + co];
                        float2 pq = *(const float2*)&g_PQ[(b * 128 + row) * NC + co];
                        stg[row * 264 + co] = 2.f * (acc[s][t][f][rh * 2] + rq.x + qb.x + pq.x);
                        stg[row * 264 + co + 1] = 2.f * (acc[s][t][f][rh * 2 + 1] + rq.y + qb.y + pq.y);
                    }
                }
    }
    __syncthreads();

    {   // LN stats: 2 threads per token
        int token = tid >> 1, q = tid & 1;
        float s = 0.f, s2 = 0.f;
#pragma unroll
        for (int jj = 0; jj < 32; jj++) {
            float4 v = *(const float4*)&stg[token * 264 + q * 128 + jj * 4];
            s += v.x + v.y + v.z + v.w;
            s2 += v.x * v.x + v.y * v.y + v.z * v.z + v.w * v.w;
        }
        s += __shfl_xor_sync(0xffffffffu, s, 1);
        s2 += __shfl_xor_sync(0xffffffffu, s2, 1);
        if (q == 0) {
            float mu = s * (1.f / 256.f);
            mus[token] = mu;
            rss[token] = rsqrtf(s2 * (1.f / 256.f) - mu * mu + 1e-5f);
        }
    }
    __syncthreads();

    {
        int t = tid & 127, cg = tid >> 7;
        float mu = mus[t], rs = rss[t];
        size_t obase = ((size_t)b * NC) * NTOK + n0 + t;
#pragma unroll 4
        for (int p = 0; p < 128; p++) {
            int co = cg * 128 + p;
            out[obase + (size_t)co * NTOK] = (stg[t * 264 + co] - mu) * rs * g_ln[co] + b_ln[co];
        }
    }
}

// ---------------- launch ----------------
extern "C" void kernel_launch(void* const* d_in, const int* in_sizes, int n_in,
                              void* d_out, int out_size) {
    const float* x    = (const float*)d_in[0];
    const float* Wq   = (const float*)d_in[1];
    const float* bq   = (const float*)d_in[2];
    const float* Wk   = (const float*)d_in[3];
    const float* bk   = (const float*)d_in[4];
    const float* Wv   = (const float*)d_in[5];
    const float* bv   = (const float*)d_in[6];
    const float* gK   = (const float*)d_in[7];
    const float* bK   = (const float*)d_in[8];
    const float* gV   = (const float*)d_in[9];
    const float* bV   = (const float*)d_in[10];
    const float* g_ln = (const float*)d_in[11];
    const float* b_ln = (const float*)d_in[12];
    float* out = (float*)d_out;

    cudaFuncSetAttribute(t1_kernel, cudaFuncAttributeMaxDynamicSharedMemorySize, T1_TOT);
    cudaFuncSetAttribute(t3_kernel, cudaFuncAttributeMaxDynamicSharedMemorySize, T3_TOT);

    prep0_kernel<<<256, 256>>>(Wk, Wv);
    prep1_kernel<<<16, 256>>>();
    t1_kernel<<<dim3(128, 8), 256, T1_TOT>>>(x, bk, bv, gK, bK, gV, bV);
    k2_reduce<<<256, 256>>>();
    k2b_buildM<<<dim3(8, 8), 256>>>(Wq, bq);
    k2c_rqpq<<<dim3(128, 8), 256>>>();
    t3_kernel<<<dim3(128, 8), 256, T3_TOT>>>(x, g_ln, b_ln, out);
}

// round 13
// speedup vs baseline: 1.0851x; 1.0851x over previous
#include <cuda_runtime.h>
#include <cuda_fp16.h>
#include <math.h>
#include <stdint.h>

#define NB 8
#define NC 256
#define NTOK 16384

__device__ __forceinline__ uint32_t s2u(const void* p) {
    uint32_t a;
    asm("{ .reg .u64 t; cvta.to.shared.u64 t, %1; cvt.u32.u64 %0, t; }" : "=r"(a) : "l"(p));
    return a;
}
__device__ __forceinline__ void ldm_x4(uint32_t r[4], uint32_t addr) {
    asm volatile("ldmatrix.sync.aligned.m8n8.x4.shared.b16 {%0,%1,%2,%3}, [%4];"
        : "=r"(r[0]), "=r"(r[1]), "=r"(r[2]), "=r"(r[3]) : "r"(addr));
}
__device__ __forceinline__ void mma_f16(float c[4], const uint32_t a[4], const uint32_t b[2]) {
    asm volatile("mma.sync.aligned.m16n8k16.row.col.f32.f16.f16.f32 "
        "{%0,%1,%2,%3}, {%4,%5,%6,%7}, {%8,%9}, {%0,%1,%2,%3};"
        : "+f"(c[0]), "+f"(c[1]), "+f"(c[2]), "+f"(c[3])
        : "r"(a[0]), "r"(a[1]), "r"(a[2]), "r"(a[3]), "r"(b[0]), "r"(b[1]));
}
__device__ __forceinline__ void cpa16(uint32_t s, const void* g) {
    asm volatile("cp.async.cg.shared.global [%0], [%1], 16;"
        :: "r"(s), "l"(__cvta_generic_to_global(g)));
}
#define CP_COMMIT() asm volatile("cp.async.commit_group;" ::: "memory")
#define CP_WAIT0() asm volatile("cp.async.wait_group 0;" ::: "memory")
#define CP_WAIT1() asm volatile("cp.async.wait_group 1;" ::: "memory")

// ---------------- device scratch ----------------
__device__ float g_T[128 * 128];
__device__ float g_WkT[NC * NC];
__device__ float g_RK[128 * NC];
__device__ float g_PK[128 * NC];
__device__ float g_spart[(size_t)NB * 256 * 8192];
__device__ float g_S[NB * 8192];
__device__ float g_M[NB * NC * NC];          // transposed [co][ci]
__device__ float g_biasq[NB * NC];
__device__ float g_RQ[NB * 128 * NC];
__device__ float g_PQ[NB * 128 * NC];
__device__ __align__(16) __half g_Bw[2][256][264];      // Wk, Wv fp16 [co][ci]
__device__ __align__(16) __half g_Bm[NB][256][264];     // M fp16 [co][ci]

// t1 smem (bytes): A@0 67584 | B@67584 (K rows 0-63, V rows 64-127) | KT@135168 | VT@152576
#define T1_B   67584
#define KT_OFF 135168
#define VT_OFF 152576
#define T1_TOT 169984
// t3 smem: A@0 | B0@67584 | B1@135168 | mus@202752 | rss@203264
#define T3_B0  67584
#define T3_B1  135168
#define T3_MU  202752
#define T3_RS  203264
#define T3_TOT 203776

// ---------------- preps ----------------
__global__ void prep0_kernel(const float* __restrict__ Wk, const float* __restrict__ Wv) {
    int idx = blockIdx.x * 256 + threadIdx.x;
    int co = idx >> 8, ci = idx & 255;
    g_WkT[ci * NC + co] = Wk[idx];
    g_Bw[0][co][ci] = __float2half_rn(Wk[idx]);
    g_Bw[1][co][ci] = __float2half_rn(Wv[idx]);
    if (idx < 128 * 128) {
        int p = idx >> 7, c = idx & 127, j = c >> 1;
        float dimt = powf(10000.0f, (float)j * (1.0f / 64.0f));
        float t = (float)(p + 1) * (6.283185307179586f / (128.0f + 1e-6f)) / dimt;
        g_T[idx] = (c & 1) ? cosf(t) : sinf(t);
    }
}

__global__ void prep1_kernel() {
    int table = blockIdx.x >> 3, chunk = blockIdx.x & 7;
    int n = chunk * 32 + (threadIdx.x & 31);
    int yg = threadIdx.x >> 5;
    float acc[16];
#pragma unroll
    for (int i = 0; i < 16; i++) acc[i] = 0.f;
    const float* W = g_WkT + (table ? 128 * NC : 0);
#pragma unroll 4
    for (int c = 0; c < 128; c++) {
        float w = W[c * NC + n];
#pragma unroll
        for (int yy = 0; yy < 16; yy++) acc[yy] += g_T[(yg * 16 + yy) * 128 + c] * w;
    }
    float* dst = table ? g_PK : g_RK;
#pragma unroll
    for (int yy = 0; yy < 16; yy++) dst[(yg * 16 + yy) * NC + n] = acc[yy];
}

// x[ci][tok] -> A[tok 128][ci 256 pad 264] fp16 (512 threads)
__device__ __forceinline__ void load_x_tile(char* smem, const float* __restrict__ xb, int tid) {
    int tok = tid & 127, cig = tid >> 7;
#pragma unroll 1
    for (int p = 0; p < 8; p++) {
        int ci0 = (cig + p * 4) * 8;
        __half hv[8];
#pragma unroll
        for (int j = 0; j < 8; j++)
            hv[j] = __float2half_rn(xb[(size_t)(ci0 + j) * NTOK + tok]);
        *(uint4*)(smem + tok * 528 + ci0 * 2) = *(uint4*)hv;
    }
}

// ---------------- T1: fp16 K/V proj (m32n32 warps) + in-reg LN + fp16 scores ----------------
__global__ void __launch_bounds__(512, 1) t1_kernel(
    const float* __restrict__ x,
    const float* __restrict__ bk, const float* __restrict__ bv,
    const float* __restrict__ gK, const float* __restrict__ bKp,
    const float* __restrict__ gV, const float* __restrict__ bVp)
{
    extern __shared__ char smem[];
    const int tid = threadIdx.x, w = tid >> 5, lane = tid & 31;
    const int rb = blockIdx.x, b = blockIdx.y;
    const int n0 = rb * 128;
    uint32_t sb = s2u(smem);

    const int op = w >> 3, mt = (w >> 1) & 3, ch = w & 1;   // K/V, m32 tile, n32 chunk
    const uint32_t aH0 = sb + (mt * 32 + (lane & 15)) * 528 + ((lane & 16) ? 16 : 0);
    const int blrow = (lane & 7) + ((lane & 16) ? 8 : 0);
    const int blcol2 = (lane & 8) ? 16 : 0;
    const uint32_t bbase = sb + T1_B + (op * 64 + ch * 32 + blrow) * 528 + blcol2;

    // pre-issue stage 0 (K+V chunk nc=0)
    for (int i = tid; i < 2112; i += 512) {
        cpa16(sb + T1_B + i * 16, ((const uint4*)&g_Bw[0][0][0]) + i);
        cpa16(sb + T1_B + 33792 + i * 16, ((const uint4*)&g_Bw[1][0][0]) + i);
    }
    CP_COMMIT();
    load_x_tile(smem, x + ((size_t)b * NC) * NTOK + n0, tid);

#pragma unroll 1
    for (int nc = 0; nc < 4; nc++) {
        CP_WAIT0();
        __syncthreads();

        float acc[2][4][4];
#pragma unroll
        for (int t = 0; t < 2; t++)
#pragma unroll
            for (int f = 0; f < 4; f++)
#pragma unroll
                for (int j = 0; j < 4; j++) acc[t][f][j] = 0.f;

#pragma unroll 4
        for (int k = 0; k < 16; k++) {
            uint32_t a0[4], a1[4];
            ldm_x4(a0, aH0 + k * 32);
            ldm_x4(a1, aH0 + 16 * 528 + k * 32);
#pragma unroll
            for (int q = 0; q < 2; q++) {
                uint32_t bb[4];
                ldm_x4(bb, bbase + q * 16 * 528 + k * 32);
                mma_f16(acc[0][q * 2], a0, bb);
                mma_f16(acc[0][q * 2 + 1], a0, bb + 2);
                mma_f16(acc[1][q * 2], a1, bb);
                mma_f16(acc[1][q * 2 + 1], a1, bb + 2);
            }
        }
        __syncthreads();   // all B reads done; buffer free for next stage

        if (nc < 3) {
            for (int i = tid; i < 2112; i += 512) {
                cpa16(sb + T1_B + i * 16, ((const uint4*)&g_Bw[0][(nc + 1) * 64][0]) + i);
                cpa16(sb + T1_B + 33792 + i * 16, ((const uint4*)&g_Bw[1][(nc + 1) * 64][0]) + i);
            }
            CP_COMMIT();
        }

        // epilogue: +pos/bias in place -> per-row LN -> transposed fp16 store (head = nc*2+ch)
        {
            const int r0 = lane >> 2, cq = (lane & 3) * 2;
            const int head = nc * 2 + ch;
            if (op == 0) {
#pragma unroll
                for (int t = 0; t < 2; t++)
#pragma unroll
                    for (int f = 0; f < 4; f++) {
                        int co = nc * 64 + ch * 32 + f * 8 + cq;
                        float2 rk = *(const float2*)&g_RK[rb * NC + co];
                        float2 bkk = *(const float2*)&bk[co];
                        int rowA = mt * 32 + t * 16 + r0;
                        float2 pa = *(const float2*)&g_PK[rowA * NC + co];
                        float2 pb = *(const float2*)&g_PK[(rowA + 8) * NC + co];
                        acc[t][f][0] += rk.x + pa.x + bkk.x;
                        acc[t][f][1] += rk.y + pa.y + bkk.y;
                        acc[t][f][2] += rk.x + pb.x + bkk.x;
                        acc[t][f][3] += rk.y + pb.y + bkk.y;
                    }
            } else {
#pragma unroll
                for (int t = 0; t < 2; t++)
#pragma unroll
                    for (int f = 0; f < 4; f++) {
                        int co = nc * 64 + ch * 32 + f * 8 + cq;
                        float2 bv2 = *(const float2*)&bv[co];
                        acc[t][f][0] += bv2.x;
                        acc[t][f][1] += bv2.y;
                        acc[t][f][2] += bv2.x;
                        acc[t][f][3] += bv2.y;
                    }
            }
            const float* gg = op ? gV : gK;
            const float* be = op ? bVp : bKp;
            float gv[8], bb8[8];
#pragma unroll
            for (int f = 0; f < 4; f++)
#pragma unroll
                for (int j = 0; j < 2; j++) {
                    gv[f * 2 + j] = gg[head * 32 + f * 8 + cq + j];
                    bb8[f * 2 + j] = be[head * 32 + f * 8 + cq + j];
                }
            uint32_t base = sb + (op ? VT_OFF : KT_OFF);
#pragma unroll
            for (int t = 0; t < 2; t++)
#pragma unroll
                for (int rh = 0; rh < 2; rh++) {
                    int row = mt * 32 + t * 16 + rh * 8 + r0;
                    float s = 0.f, q2 = 0.f;
#pragma unroll
                    for (int f = 0; f < 4; f++)
#pragma unroll
                        for (int j = 0; j < 2; j++) {
                            float a = acc[t][f][rh * 2 + j];
                            s += a; q2 += a * a;
                        }
#pragma unroll
                    for (int off = 1; off < 4; off <<= 1) {
                        s += __shfl_xor_sync(0xffffffffu, s, off);
                        q2 += __shfl_xor_sync(0xffffffffu, q2, off);
                    }
                    float mu = s * (1.f / 32.f);
                    float rs = rsqrtf(q2 * (1.f / 32.f) - mu * mu + 1e-5f);
#pragma unroll
                    for (int f = 0; f < 4; f++)
#pragma unroll
                        for (int j = 0; j < 2; j++) {
                            int d = ch * 32 + f * 8 + cq + j;
                            __half h = __float2half_rn(
                                (acc[t][f][rh * 2 + j] - mu) * rs * gv[f * 2 + j] + bb8[f * 2 + j]);
                            asm volatile("st.shared.u16 [%0], %1;"
                                :: "r"(base + (uint32_t)d * 272 + row * 2), "h"(*(unsigned short*)&h));
                        }
                }
        }
        __syncthreads();

        // scores (all 16 warps, token-split): S_h[d][e] += sum K[tok][d] V[tok][e]
        {
            const int khalf = w >> 3, hl = (w >> 2) & 1, dt = (w >> 1) & 1, et = w & 1;
            const uint32_t aB = sb + KT_OFF + (hl * 32 + dt * 16 + (lane & 15)) * 272
                              + khalf * 128 + ((lane & 16) ? 16 : 0);
            const uint32_t bB = sb + VT_OFF + (hl * 32 + et * 16 + blrow) * 272
                              + khalf * 128 + blcol2;
            float sc[2][4];
#pragma unroll
            for (int q = 0; q < 2; q++)
#pragma unroll
                for (int j = 0; j < 4; j++) sc[q][j] = 0.f;
#pragma unroll
            for (int k = 0; k < 4; k++) {
                uint32_t a[4], bb[4];
                ldm_x4(a, aB + k * 32);
                ldm_x4(bb, bB + k * 32);
                mma_f16(sc[0], a, bb);
                mma_f16(sc[1], a, bb + 2);
            }
            float* dst = g_spart + ((size_t)(b * 256 + rb * 2 + khalf)) * 8192 + (nc * 2 + hl) * 1024;
            int d0 = dt * 16 + (lane >> 2);
#pragma unroll
            for (int q = 0; q < 2; q++) {
                int e0 = et * 16 + q * 8 + (lane & 3) * 2;
                dst[d0 * 32 + e0] = sc[q][0];
                dst[d0 * 32 + e0 + 1] = sc[q][1];
                dst[(d0 + 8) * 32 + e0] = sc[q][2];
                dst[(d0 + 8) * 32 + e0 + 1] = sc[q][3];
            }
        }
    }
}

// ---------------- k2 chain ----------------
__global__ void k2_reduce() {
    int b = blockIdx.x >> 5, seg = blockIdx.x & 31;
    int base = seg * 256 + threadIdx.x;
    float s = 0.f;
#pragma unroll 8
    for (int rb = 0; rb < 256; rb++) s += g_spart[((size_t)(b * 256 + rb)) * 8192 + base];
    g_S[b * 8192 + base] = s * (1.0f / 16384.0f);
}

__global__ void k2b_buildM(const float* __restrict__ Wq, const float* __restrict__ bq) {
    __shared__ float Wqs[256 * 33];
    int chunk = blockIdx.x, b = blockIdx.y;
    int co = threadIdx.x, h = co >> 5, e = co & 31;
    for (int idx = threadIdx.x; idx < 8192; idx += 256) {
        int row = idx >> 5, cil = idx & 31;
        Wqs[row * 33 + cil] = Wq[row * NC + chunk * 32 + cil];
    }
    float Scol[32];
#pragma unroll
    for (int d = 0; d < 32; d++) Scol[d] = g_S[b * 8192 + h * 1024 + d * 32 + e];
    __syncthreads();
    for (int cil = 0; cil < 32; cil++) {
        float m = 0.f;
#pragma unroll
        for (int d = 0; d < 32; d++) m += Wqs[(h * 32 + d) * 33 + cil] * Scol[d];
        g_M[(size_t)b * 65536 + (size_t)co * NC + chunk * 32 + cil] = m;
        g_Bm[b][co][chunk * 32 + cil] = __float2half_rn(m);
    }
    if (chunk == 0) {
        float bb = 0.f;
#pragma unroll
        for (int d = 0; d < 32; d++) bb += bq[h * 32 + d] * Scol[d];
        g_biasq[b * NC + co] = bb;
    }
}

__global__ void k2c_rqpq() {
    __shared__ float Ts[128];
    int p = blockIdx.x, b = blockIdx.y;
    int co = threadIdx.x;
    if (co < 128) Ts[co] = g_T[p * 128 + co];
    __syncthreads();
    const float4* Mr = (const float4*)(g_M + (size_t)b * 65536 + (size_t)co * NC);
    float accR = 0.f, accP = 0.f;
#pragma unroll 8
    for (int c4 = 0; c4 < 32; c4++) {
        float4 m0 = Mr[c4], m1 = Mr[32 + c4];
        float4 t4 = *(const float4*)&Ts[c4 * 4];
        accR += t4.x * m0.x + t4.y * m0.y + t4.z * m0.z + t4.w * m0.w;
        accP += t4.x * m1.x + t4.y * m1.y + t4.z * m1.z + t4.w * m1.w;
    }
    g_RQ[(b * 128 + p) * NC + co] = accR;
    g_PQ[(b * 128 + p) * NC + co] = accP;
}

// ---------------- T3: fp16 out GEMM (m32n32 warps, 2 double-buffered stages) ----------------
__global__ void __launch_bounds__(512, 1) t3_kernel(
    const float* __restrict__ x,
    const float* __restrict__ g_ln, const float* __restrict__ b_ln,
    float* __restrict__ out)
{
    extern __shared__ char smem[];
    const int tid = threadIdx.x, w = tid >> 5, lane = tid & 31;
    const int rb = blockIdx.x, b = blockIdx.y;
    const int n0 = rb * 128;
    uint32_t sb = s2u(smem);

    const int mt = w >> 2, ch = w & 3;      // m32 tile, n32 chunk within 128-co stage
    const uint32_t aH0 = sb + (mt * 32 + (lane & 15)) * 528 + ((lane & 16) ? 16 : 0);
    const int blrow = (lane & 7) + ((lane & 16) ? 8 : 0);
    const int blcol2 = (lane & 8) ? 16 : 0;

    for (int i = tid; i < 4224; i += 512)
        cpa16(sb + T3_B0 + i * 16, ((const uint4*)&g_Bm[b][0][0]) + i);
    CP_COMMIT();
    load_x_tile(smem, x + ((size_t)b * NC) * NTOK + n0, tid);
    for (int i = tid; i < 4224; i += 512)
        cpa16(sb + T3_B1 + i * 16, ((const uint4*)&g_Bm[b][128][0]) + i);
    CP_COMMIT();

    float acc[2][2][4][4];
#pragma unroll 1
    for (int s = 0; s < 2; s++) {
        if (s == 0) CP_WAIT1(); else CP_WAIT0();
        __syncthreads();
#pragma unroll
        for (int t = 0; t < 2; t++)
#pragma unroll
            for (int f = 0; f < 4; f++)
#pragma unroll
                for (int j = 0; j < 4; j++) acc[s][t][f][j] = 0.f;

        const uint32_t bbase = sb + (s ? T3_B1 : T3_B0) + (ch * 32 + blrow) * 528 + blcol2;
#pragma unroll 4
        for (int k = 0; k < 16; k++) {
            uint32_t a0[4], a1[4];
            ldm_x4(a0, aH0 + k * 32);
            ldm_x4(a1, aH0 + 16 * 528 + k * 32);
#pragma unroll
            for (int q = 0; q < 2; q++) {
                uint32_t bb[4];
                ldm_x4(bb, bbase + q * 16 * 528 + k * 32);
                mma_f16(acc[s][0][q * 2], a0, bb);
                mma_f16(acc[s][0][q * 2 + 1], a0, bb + 2);
                mma_f16(acc[s][1][q * 2], a1, bb);
                mma_f16(acc[s][1][q * 2 + 1], a1, bb + 2);
            }
        }
    }
    __syncthreads();

    float* stg = (float*)smem;          // [128][264] overlays A+B0
    float* mus = (float*)(smem + T3_MU);
    float* rss = (float*)(smem + T3_RS);
    {
        int r0 = lane >> 2, cq = (lane & 3) * 2;
#pragma unroll
        for (int s = 0; s < 2; s++)
#pragma unroll
            for (int t = 0; t < 2; t++)
#pragma unroll
                for (int rh = 0; rh < 2; rh++) {
                    int row = mt * 32 + t * 16 + rh * 8 + r0;
#pragma unroll
                    for (int f = 0; f < 4; f++) {
                        int co = s * 128 + ch * 32 + f * 8 + cq;
                        float2 rq = *(const float2*)&g_RQ[(b * 128 + rb) * NC + co];
                        float2 qb = *(const float2*)&g_biasq[b * NC + co];
                        float2 pq = *(const float2*)&g_PQ[(b * 128 + row) * NC + co];
                        stg[row * 264 + co] = 2.f * (acc[s][t][f][rh * 2] + rq.x + qb.x + pq.x);
                        stg[row * 264 + co + 1] = 2.f * (acc[s][t][f][rh * 2 + 1] + rq.y + qb.y + pq.y);
                    }
                }
    }
    __syncthreads();

    {   // LN stats: 4 threads per token
        int token = tid >> 2, q = tid & 3;
        float s = 0.f, s2 = 0.f;
#pragma unroll
        for (int jj = 0; jj < 16; jj++) {
            float4 v = *(const float4*)&stg[token * 264 + q * 64 + jj * 4];
            s += v.x + v.y + v.z + v.w;
            s2 += v.x * v.x + v.y * v.y + v.z * v.z + v.w * v.w;
        }
#pragma unroll
        for (int off = 1; off < 4; off <<= 1) {
            s += __shfl_xor_sync(0xffffffffu, s, off);
            s2 += __shfl_xor_sync(0xffffffffu, s2, off);
        }
        if (q == 0) {
            float mu = s * (1.f / 256.f);
            mus[token] = mu;
            rss[token] = rsqrtf(s2 * (1.f / 256.f) - mu * mu + 1e-5f);
        }
    }
    __syncthreads();

    {
        int t = tid & 127, cg = tid >> 7;
        float mu = mus[t], rs = rss[t];
        size_t obase = ((size_t)b * NC) * NTOK + n0 + t;
#pragma unroll 4
        for (int p = 0; p < 64; p++) {
            int co = cg * 64 + p;
            out[obase + (size_t)co * NTOK] = (stg[t * 264 + co] - mu) * rs * g_ln[co] + b_ln[co];
        }
    }
}

// ---------------- launch ----------------
extern "C" void kernel_launch(void* const* d_in, const int* in_sizes, int n_in,
                              void* d_out, int out_size) {
    const float* x    = (const float*)d_in[0];
    const float* Wq   = (const float*)d_in[1];
    const float* bq   = (const float*)d_in[2];
    const float* Wk   = (const float*)d_in[3];
    const float* bk   = (const float*)d_in[4];
    const float* Wv   = (const float*)d_in[5];
    const float* bv   = (const float*)d_in[6];
    const float* gK   = (const float*)d_in[7];
    const float* bK   = (const float*)d_in[8];
    const float* gV   = (const float*)d_in[9];
    const float* bV   = (const float*)d_in[10];
    const float* g_ln = (const float*)d_in[11];
    const float* b_ln = (const float*)d_in[12];
    float* out = (float*)d_out;

    cudaFuncSetAttribute(t1_kernel, cudaFuncAttributeMaxDynamicSharedMemorySize, T1_TOT);
    cudaFuncSetAttribute(t3_kernel, cudaFuncAttributeMaxDynamicSharedMemorySize, T3_TOT);

    prep0_kernel<<<256, 256>>>(Wk, Wv);
    prep1_kernel<<<16, 256>>>();
    t1_kernel<<<dim3(128, 8), 512, T1_TOT>>>(x, bk, bv, gK, bK, gV, bV);
    k2_reduce<<<256, 256>>>();
    k2b_buildM<<<dim3(8, 8), 256>>>(Wq, bq);
    k2c_rqpq<<<dim3(128, 8), 256>>>();
    t3_kernel<<<dim3(128, 8), 512, T3_TOT>>>(x, g_ln, b_ln, out);
}

// round 14
// speedup vs baseline: 1.2313x; 1.1347x over previous
#include <cuda_runtime.h>
#include <cuda_fp16.h>
#include <math.h>
#include <stdint.h>

#define NB 8
#define NC 256
#define NTOK 16384

__device__ __forceinline__ uint32_t s2u(const void* p) {
    uint32_t a;
    asm("{ .reg .u64 t; cvta.to.shared.u64 t, %1; cvt.u32.u64 %0, t; }" : "=r"(a) : "l"(p));
    return a;
}
__device__ __forceinline__ void ldm_x4(uint32_t r[4], uint32_t addr) {
    asm volatile("ldmatrix.sync.aligned.m8n8.x4.shared.b16 {%0,%1,%2,%3}, [%4];"
        : "=r"(r[0]), "=r"(r[1]), "=r"(r[2]), "=r"(r[3]) : "r"(addr));
}
__device__ __forceinline__ void mma_f16(float c[4], const uint32_t a[4], const uint32_t b[2]) {
    asm volatile("mma.sync.aligned.m16n8k16.row.col.f32.f16.f16.f32 "
        "{%0,%1,%2,%3}, {%4,%5,%6,%7}, {%8,%9}, {%0,%1,%2,%3};"
        : "+f"(c[0]), "+f"(c[1]), "+f"(c[2]), "+f"(c[3])
        : "r"(a[0]), "r"(a[1]), "r"(a[2]), "r"(a[3]), "r"(b[0]), "r"(b[1]));
}
__device__ __forceinline__ void cpa16(uint32_t s, const void* g) {
    asm volatile("cp.async.cg.shared.global [%0], [%1], 16;"
        :: "r"(s), "l"(__cvta_generic_to_global(g)));
}
#define CP_COMMIT() asm volatile("cp.async.commit_group;" ::: "memory")
#define CP_WAIT0() asm volatile("cp.async.wait_group 0;" ::: "memory")
#define CP_WAIT1() asm volatile("cp.async.wait_group 1;" ::: "memory")

// ---------------- device scratch ----------------
__device__ float g_T[128 * 128];
__device__ float g_WkT[NC * NC];
__device__ float g_RK[128 * NC];
__device__ float g_PK[128 * NC];
__device__ float g_spart[(size_t)NB * 128 * 8192];
__device__ float g_S[NB * 8192];
__device__ float g_M[NB * NC * NC];          // transposed [co][ci]
__device__ float g_biasq[NB * NC];
__device__ float g_RQ[NB * 128 * NC];
__device__ float g_PQ[NB * 128 * NC];
__device__ __align__(16) __half g_Bw[2][256][264];      // Wk, Wv fp16 [co][ci]
__device__ __align__(16) __half g_Bm[NB][256][264];     // M fp16 [co][ci]

// t1 smem (bytes): A@0 67584 | B@67584 (K rows 0-63, V rows 64-127) | KT@135168 | VT@152576 | SC@169984
#define T1_B   67584
#define KT_OFF 135168
#define VT_OFF 152576
#define SC_OFF 169984
#define T1_TOT 178176
// t3 smem: A@0 | B0@67584 | B1@135168 | mus@202752 | rss@203264
#define T3_B0  67584
#define T3_B1  135168
#define T3_MU  202752
#define T3_RS  203264
#define T3_TOT 203776

// ---------------- preps ----------------
__global__ void prep0_kernel(const float* __restrict__ Wk, const float* __restrict__ Wv) {
    int idx = blockIdx.x * 256 + threadIdx.x;
    int co = idx >> 8, ci = idx & 255;
    g_WkT[ci * NC + co] = Wk[idx];
    g_Bw[0][co][ci] = __float2half_rn(Wk[idx]);
    g_Bw[1][co][ci] = __float2half_rn(Wv[idx]);
    if (idx < 128 * 128) {
        int p = idx >> 7, c = idx & 127, j = c >> 1;
        float dimt = powf(10000.0f, (float)j * (1.0f / 64.0f));
        float t = (float)(p + 1) * (6.283185307179586f / (128.0f + 1e-6f)) / dimt;
        g_T[idx] = (c & 1) ? cosf(t) : sinf(t);
    }
}

__global__ void prep1_kernel() {
    int table = blockIdx.x >> 3, chunk = blockIdx.x & 7;
    int n = chunk * 32 + (threadIdx.x & 31);
    int yg = threadIdx.x >> 5;
    float acc[16];
#pragma unroll
    for (int i = 0; i < 16; i++) acc[i] = 0.f;
    const float* W = g_WkT + (table ? 128 * NC : 0);
#pragma unroll 4
    for (int c = 0; c < 128; c++) {
        float w = W[c * NC + n];
#pragma unroll
        for (int yy = 0; yy < 16; yy++) acc[yy] += g_T[(yg * 16 + yy) * 128 + c] * w;
    }
    float* dst = table ? g_PK : g_RK;
#pragma unroll
    for (int yy = 0; yy < 16; yy++) dst[(yg * 16 + yy) * NC + n] = acc[yy];
}

// x[ci][tok] -> A[tok 128][ci 256 pad 264] fp16 (512 threads)
__device__ __forceinline__ void load_x_tile(char* smem, const float* __restrict__ xb, int tid) {
    int tok = tid & 127, cig = tid >> 7;
#pragma unroll 1
    for (int p = 0; p < 8; p++) {
        int ci0 = (cig + p * 4) * 8;
        __half hv[8];
#pragma unroll
        for (int j = 0; j < 8; j++)
            hv[j] = __float2half_rn(xb[(size_t)(ci0 + j) * NTOK + tok]);
        *(uint4*)(smem + tok * 528 + ci0 * 2) = *(uint4*)hv;
    }
}

// ---------------- T1: fp16 K/V proj (m32n32 warps) + in-reg LN + fp16 scores ----------------
__global__ void __launch_bounds__(512, 1) t1_kernel(
    const float* __restrict__ x,
    const float* __restrict__ bk, const float* __restrict__ bv,
    const float* __restrict__ gK, const float* __restrict__ bKp,
    const float* __restrict__ gV, const float* __restrict__ bVp)
{
    extern __shared__ char smem[];
    const int tid = threadIdx.x, w = tid >> 5, lane = tid & 31;
    const int rb = blockIdx.x, b = blockIdx.y;
    const int n0 = rb * 128;
    uint32_t sb = s2u(smem);

    const int op = w >> 3, mt = (w >> 1) & 3, ch = w & 1;   // K/V, m32 tile, n32 chunk
    const uint32_t aH0 = sb + (mt * 32 + (lane & 15)) * 528 + ((lane & 16) ? 16 : 0);
    const int blrow = (lane & 7) + ((lane & 16) ? 8 : 0);
    const int blcol2 = (lane & 8) ? 16 : 0;
    const uint32_t bbase = sb + T1_B + (op * 64 + ch * 32 + blrow) * 528 + blcol2;

    // pre-issue stage 0 (K+V chunk nc=0)
    for (int i = tid; i < 2112; i += 512) {
        cpa16(sb + T1_B + i * 16, ((const uint4*)&g_Bw[0][0][0]) + i);
        cpa16(sb + T1_B + 33792 + i * 16, ((const uint4*)&g_Bw[1][0][0]) + i);
    }
    CP_COMMIT();
    load_x_tile(smem, x + ((size_t)b * NC) * NTOK + n0, tid);

#pragma unroll 1
    for (int nc = 0; nc < 4; nc++) {
        CP_WAIT0();
        __syncthreads();

        float acc[2][4][4];
#pragma unroll
        for (int t = 0; t < 2; t++)
#pragma unroll
            for (int f = 0; f < 4; f++)
#pragma unroll
                for (int j = 0; j < 4; j++) acc[t][f][j] = 0.f;

#pragma unroll 4
        for (int k = 0; k < 16; k++) {
            uint32_t a0[4], a1[4];
            ldm_x4(a0, aH0 + k * 32);
            ldm_x4(a1, aH0 + 16 * 528 + k * 32);
#pragma unroll
            for (int q = 0; q < 2; q++) {
                uint32_t bb[4];
                ldm_x4(bb, bbase + q * 16 * 528 + k * 32);
                mma_f16(acc[0][q * 2], a0, bb);
                mma_f16(acc[0][q * 2 + 1], a0, bb + 2);
                mma_f16(acc[1][q * 2], a1, bb);
                mma_f16(acc[1][q * 2 + 1], a1, bb + 2);
            }
        }
        __syncthreads();   // all B reads done; buffer free for next stage

        if (nc < 3) {
            for (int i = tid; i < 2112; i += 512) {
                cpa16(sb + T1_B + i * 16, ((const uint4*)&g_Bw[0][(nc + 1) * 64][0]) + i);
                cpa16(sb + T1_B + 33792 + i * 16, ((const uint4*)&g_Bw[1][(nc + 1) * 64][0]) + i);
            }
            CP_COMMIT();
        }

        // epilogue: +pos/bias in place -> per-row LN -> transposed fp16 store (head = nc*2+ch)
        {
            const int r0 = lane >> 2, cq = (lane & 3) * 2;
            const int head = nc * 2 + ch;
            if (op == 0) {
#pragma unroll
                for (int t = 0; t < 2; t++)
#pragma unroll
                    for (int f = 0; f < 4; f++) {
                        int co = nc * 64 + ch * 32 + f * 8 + cq;
                        float2 rk = *(const float2*)&g_RK[rb * NC + co];
                        float2 bkk = *(const float2*)&bk[co];
                        int rowA = mt * 32 + t * 16 + r0;
                        float2 pa = *(const float2*)&g_PK[rowA * NC + co];
                        float2 pb = *(const float2*)&g_PK[(rowA + 8) * NC + co];
                        acc[t][f][0] += rk.x + pa.x + bkk.x;
                        acc[t][f][1] += rk.y + pa.y + bkk.y;
                        acc[t][f][2] += rk.x + pb.x + bkk.x;
                        acc[t][f][3] += rk.y + pb.y + bkk.y;
                    }
            } else {
#pragma unroll
                for (int t = 0; t < 2; t++)
#pragma unroll
                    for (int f = 0; f < 4; f++) {
                        int co = nc * 64 + ch * 32 + f * 8 + cq;
                        float2 bv2 = *(const float2*)&bv[co];
                        acc[t][f][0] += bv2.x;
                        acc[t][f][1] += bv2.y;
                        acc[t][f][2] += bv2.x;
                        acc[t][f][3] += bv2.y;
                    }
            }
            const float* gg = op ? gV : gK;
            const float* be = op ? bVp : bKp;
            float gv[8], bb8[8];
#pragma unroll
            for (int f = 0; f < 4; f++)
#pragma unroll
                for (int j = 0; j < 2; j++) {
                    gv[f * 2 + j] = gg[head * 32 + f * 8 + cq + j];
                    bb8[f * 2 + j] = be[head * 32 + f * 8 + cq + j];
                }
            uint32_t base = sb + (op ? VT_OFF : KT_OFF);
#pragma unroll
            for (int t = 0; t < 2; t++)
#pragma unroll
                for (int rh = 0; rh < 2; rh++) {
                    int row = mt * 32 + t * 16 + rh * 8 + r0;
                    float s = 0.f, q2 = 0.f;
#pragma unroll
                    for (int f = 0; f < 4; f++)
#pragma unroll
                        for (int j = 0; j < 2; j++) {
                            float a = acc[t][f][rh * 2 + j];
                            s += a; q2 += a * a;
                        }
#pragma unroll
                    for (int off = 1; off < 4; off <<= 1) {
                        s += __shfl_xor_sync(0xffffffffu, s, off);
                        q2 += __shfl_xor_sync(0xffffffffu, q2, off);
                    }
                    float mu = s * (1.f / 32.f);
                    float rs = rsqrtf(q2 * (1.f / 32.f) - mu * mu + 1e-5f);
#pragma unroll
                    for (int f = 0; f < 4; f++)
#pragma unroll
                        for (int j = 0; j < 2; j++) {
                            int d = ch * 32 + f * 8 + cq + j;
                            __half h = __float2half_rn(
                                (acc[t][f][rh * 2 + j] - mu) * rs * gv[f * 2 + j] + bb8[f * 2 + j]);
                            asm volatile("st.shared.u16 [%0], %1;"
                                :: "r"(base + (uint32_t)d * 272 + row * 2), "h"(*(unsigned short*)&h));
                        }
                }
        }
        __syncthreads();

        // scores (16 warps, token-split, combined via smem scratch)
        {
            const int khalf = w >> 3, hl = (w >> 2) & 1, dt = (w >> 1) & 1, et = w & 1;
            const uint32_t aB = sb + KT_OFF + (hl * 32 + dt * 16 + (lane & 15)) * 272
                              + khalf * 128 + ((lane & 16) ? 16 : 0);
            const uint32_t bB = sb + VT_OFF + (hl * 32 + et * 16 + blrow) * 272
                              + khalf * 128 + blcol2;
            float sc[2][4];
#pragma unroll
            for (int q = 0; q < 2; q++)
#pragma unroll
                for (int j = 0; j < 4; j++) sc[q][j] = 0.f;
#pragma unroll
            for (int k = 0; k < 4; k++) {
                uint32_t a[4], bb[4];
                ldm_x4(a, aB + k * 32);
                ldm_x4(bb, bB + k * 32);
                mma_f16(sc[0], a, bb);
                mma_f16(sc[1], a, bb + 2);
            }
            float* scratch = (float*)(smem + SC_OFF);   // [2 heads][1024]
            int d0 = dt * 16 + (lane >> 2);
            if (khalf == 1) {
#pragma unroll
                for (int q = 0; q < 2; q++) {
                    int e0 = et * 16 + q * 8 + (lane & 3) * 2;
                    scratch[hl * 1024 + d0 * 32 + e0] = sc[q][0];
                    scratch[hl * 1024 + d0 * 32 + e0 + 1] = sc[q][1];
                    scratch[hl * 1024 + (d0 + 8) * 32 + e0] = sc[q][2];
                    scratch[hl * 1024 + (d0 + 8) * 32 + e0 + 1] = sc[q][3];
                }
            }
            __syncthreads();
            if (khalf == 0) {
                float* dst = g_spart + ((size_t)(b * 128 + rb)) * 8192 + (nc * 2 + hl) * 1024;
#pragma unroll
                for (int q = 0; q < 2; q++) {
                    int e0 = et * 16 + q * 8 + (lane & 3) * 2;
                    dst[d0 * 32 + e0] = sc[q][0] + scratch[hl * 1024 + d0 * 32 + e0];
                    dst[d0 * 32 + e0 + 1] = sc[q][1] + scratch[hl * 1024 + d0 * 32 + e0 + 1];
                    dst[(d0 + 8) * 32 + e0] = sc[q][2] + scratch[hl * 1024 + (d0 + 8) * 32 + e0];
                    dst[(d0 + 8) * 32 + e0 + 1] = sc[q][3] + scratch[hl * 1024 + (d0 + 8) * 32 + e0 + 1];
                }
            }
        }
    }
}

// ---------------- k2 chain ----------------
__global__ void k2_reduce() {
    int b = blockIdx.x >> 5, seg = blockIdx.x & 31;
    int base = seg * 256 + threadIdx.x;
    float s = 0.f;
#pragma unroll 8
    for (int rb = 0; rb < 128; rb++) s += g_spart[((size_t)(b * 128 + rb)) * 8192 + base];
    g_S[b * 8192 + base] = s * (1.0f / 16384.0f);
}

__global__ void k2b_buildM(const float* __restrict__ Wq, const float* __restrict__ bq) {
    __shared__ float Wqs[256 * 33];
    int chunk = blockIdx.x, b = blockIdx.y;
    int co = threadIdx.x, h = co >> 5, e = co & 31;
    for (int idx = threadIdx.x; idx < 8192; idx += 256) {
        int row = idx >> 5, cil = idx & 31;
        Wqs[row * 33 + cil] = Wq[row * NC + chunk * 32 + cil];
    }
    float Scol[32];
#pragma unroll
    for (int d = 0; d < 32; d++) Scol[d] = g_S[b * 8192 + h * 1024 + d * 32 + e];
    __syncthreads();
    for (int cil = 0; cil < 32; cil++) {
        float m = 0.f;
#pragma unroll
        for (int d = 0; d < 32; d++) m += Wqs[(h * 32 + d) * 33 + cil] * Scol[d];
        g_M[(size_t)b * 65536 + (size_t)co * NC + chunk * 32 + cil] = m;
        g_Bm[b][co][chunk * 32 + cil] = __float2half_rn(m);
    }
    if (chunk == 0) {
        float bb = 0.f;
#pragma unroll
        for (int d = 0; d < 32; d++) bb += bq[h * 32 + d] * Scol[d];
        g_biasq[b * NC + co] = bb;
    }
}

// grid (16, 8): 8 p-values per block; M read once per block
__global__ void k2c_rqpq() {
    __shared__ float Ts[8][128];
    int pg = blockIdx.x, b = blockIdx.y;
    int co = threadIdx.x;
    for (int i = threadIdx.x; i < 1024; i += 256)
        Ts[i >> 7][i & 127] = g_T[(pg * 8 + (i >> 7)) * 128 + (i & 127)];
    __syncthreads();
    const float4* Mr = (const float4*)(g_M + (size_t)b * 65536 + (size_t)co * NC);
    float aR[8], aP[8];
#pragma unroll
    for (int p = 0; p < 8; p++) { aR[p] = 0.f; aP[p] = 0.f; }
#pragma unroll 4
    for (int c4 = 0; c4 < 32; c4++) {
        float4 m0 = Mr[c4], m1 = Mr[32 + c4];
        float mm0[4] = {m0.x, m0.y, m0.z, m0.w};
        float mm1[4] = {m1.x, m1.y, m1.z, m1.w};
#pragma unroll
        for (int j = 0; j < 4; j++) {
            int c = c4 * 4 + j;
#pragma unroll
            for (int p = 0; p < 8; p++) {
                float tv = Ts[p][c];
                aR[p] += tv * mm0[j];
                aP[p] += tv * mm1[j];
            }
        }
    }
#pragma unroll
    for (int p = 0; p < 8; p++) {
        g_RQ[(b * 128 + pg * 8 + p) * NC + co] = aR[p];
        g_PQ[(b * 128 + pg * 8 + p) * NC + co] = aP[p];
    }
}

// ---------------- T3: fp16 out GEMM (m32n32 warps, 2 double-buffered stages) ----------------
__global__ void __launch_bounds__(512, 1) t3_kernel(
    const float* __restrict__ x,
    const float* __restrict__ g_ln, const float* __restrict__ b_ln,
    float* __restrict__ out)
{
    extern __shared__ char smem[];
    const int tid = threadIdx.x, w = tid >> 5, lane = tid & 31;
    const int rb = blockIdx.x, b = blockIdx.y;
    const int n0 = rb * 128;
    uint32_t sb = s2u(smem);

    const int mt = w >> 2, ch = w & 3;      // m32 tile, n32 chunk within 128-co stage
    const uint32_t aH0 = sb + (mt * 32 + (lane & 15)) * 528 + ((lane & 16) ? 16 : 0);
    const int blrow = (lane & 7) + ((lane & 16) ? 8 : 0);
    const int blcol2 = (lane & 8) ? 16 : 0;

    for (int i = tid; i < 4224; i += 512)
        cpa16(sb + T3_B0 + i * 16, ((const uint4*)&g_Bm[b][0][0]) + i);
    CP_COMMIT();
    load_x_tile(smem, x + ((size_t)b * NC) * NTOK + n0, tid);
    for (int i = tid; i < 4224; i += 512)
        cpa16(sb + T3_B1 + i * 16, ((const uint4*)&g_Bm[b][128][0]) + i);
    CP_COMMIT();

    float acc[2][2][4][4];
#pragma unroll 1
    for (int s = 0; s < 2; s++) {
        if (s == 0) CP_WAIT1(); else CP_WAIT0();
        __syncthreads();
#pragma unroll
        for (int t = 0; t < 2; t++)
#pragma unroll
            for (int f = 0; f < 4; f++)
#pragma unroll
                for (int j = 0; j < 4; j++) acc[s][t][f][j] = 0.f;

        const uint32_t bbase = sb + (s ? T3_B1 : T3_B0) + (ch * 32 + blrow) * 528 + blcol2;
#pragma unroll 4
        for (int k = 0; k < 16; k++) {
            uint32_t a0[4], a1[4];
            ldm_x4(a0, aH0 + k * 32);
            ldm_x4(a1, aH0 + 16 * 528 + k * 32);
#pragma unroll
            for (int q = 0; q < 2; q++) {
                uint32_t bb[4];
                ldm_x4(bb, bbase + q * 16 * 528 + k * 32);
                mma_f16(acc[s][0][q * 2], a0, bb);
                mma_f16(acc[s][0][q * 2 + 1], a0, bb + 2);
                mma_f16(acc[s][1][q * 2], a1, bb);
                mma_f16(acc[s][1][q * 2 + 1], a1, bb + 2);
            }
        }
    }
    __syncthreads();

    float* stg = (float*)smem;          // [128][264] overlays A+B0
    float* mus = (float*)(smem + T3_MU);
    float* rss = (float*)(smem + T3_RS);
    {
        int r0 = lane >> 2, cq = (lane & 3) * 2;
#pragma unroll
        for (int s = 0; s < 2; s++)
#pragma unroll
            for (int t = 0; t < 2; t++)
#pragma unroll
                for (int rh = 0; rh < 2; rh++) {
                    int row = mt * 32 + t * 16 + rh * 8 + r0;
#pragma unroll
                    for (int f = 0; f < 4; f++) {
                        int co = s * 128 + ch * 32 + f * 8 + cq;
                        float2 rq = *(const float2*)&g_RQ[(b * 128 + rb) * NC + co];
                        float2 qb = *(const float2*)&g_biasq[b * NC + co];
                        float2 pq = *(const float2*)&g_PQ[(b * 128 + row) * NC + co];
                        stg[row * 264 + co] = 2.f * (acc[s][t][f][rh * 2] + rq.x + qb.x + pq.x);
                        stg[row * 264 + co + 1] = 2.f * (acc[s][t][f][rh * 2 + 1] + rq.y + qb.y + pq.y);
                    }
                }
    }
    __syncthreads();

    {   // LN stats: 4 threads per token
        int token = tid >> 2, q = tid & 3;
        float s = 0.f, s2 = 0.f;
#pragma unroll
        for (int jj = 0; jj < 16; jj++) {
            float4 v = *(const float4*)&stg[token * 264 + q * 64 + jj * 4];
            s += v.x + v.y + v.z + v.w;
            s2 += v.x * v.x + v.y * v.y + v.z * v.z + v.w * v.w;
        }
#pragma unroll
        for (int off = 1; off < 4; off <<= 1) {
            s += __shfl_xor_sync(0xffffffffu, s, off);
            s2 += __shfl_xor_sync(0xffffffffu, s2, off);
        }
        if (q == 0) {
            float mu = s * (1.f / 256.f);
            mus[token] = mu;
            rss[token] = rsqrtf(s2 * (1.f / 256.f) - mu * mu + 1e-5f);
        }
    }
    __syncthreads();

    {
        int t = tid & 127, cg = tid >> 7;
        float mu = mus[t], rs = rss[t];
        size_t obase = ((size_t)b * NC) * NTOK + n0 + t;
#pragma unroll 4
        for (int p = 0; p < 64; p++) {
            int co = cg * 64 + p;
            out[obase + (size_t)co * NTOK] = (stg[t * 264 + co] - mu) * rs * g_ln[co] + b_ln[co];
        }
    }
}

// ---------------- launch ----------------
extern "C" void kernel_launch(void* const* d_in, const int* in_sizes, int n_in,
                              void* d_out, int out_size) {
    const float* x    = (const float*)d_in[0];
    const float* Wq   = (const float*)d_in[1];
    const float* bq   = (const float*)d_in[2];
    const float* Wk   = (const float*)d_in[3];
    const float* bk   = (const float*)d_in[4];
    const float* Wv   = (const float*)d_in[5];
    const float* bv   = (const float*)d_in[6];
    const float* gK   = (const float*)d_in[7];
    const float* bK   = (const float*)d_in[8];
    const float* gV   = (const float*)d_in[9];
    const float* bV   = (const float*)d_in[10];
    const float* g_ln = (const float*)d_in[11];
    const float* b_ln = (const float*)d_in[12];
    float* out = (float*)d_out;

    cudaFuncSetAttribute(t1_kernel, cudaFuncAttributeMaxDynamicSharedMemorySize, T1_TOT);
    cudaFuncSetAttribute(t3_kernel, cudaFuncAttributeMaxDynamicSharedMemorySize, T3_TOT);

    prep0_kernel<<<256, 256>>>(Wk, Wv);
    prep1_kernel<<<16, 256>>>();
    t1_kernel<<<dim3(128, 8), 512, T1_TOT>>>(x, bk, bv, gK, bK, gV, bV);
    k2_reduce<<<256, 256>>>();
    k2b_buildM<<<dim3(8, 8), 256>>>(Wq, bq);
    k2c_rqpq<<<dim3(16, 8), 256>>>();
    t3_kernel<<<dim3(128, 8), 512, T3_TOT>>>(x, g_ln, b_ln, out);
}

// round 15
// speedup vs baseline: 1.2736x; 1.0343x over previous
#include <cuda_runtime.h>
#include <cuda_fp16.h>
#include <math.h>
#include <stdint.h>

#define NB 8
#define NC 256
#define NTOK 16384

__device__ __forceinline__ uint32_t s2u(const void* p) {
    uint32_t a;
    asm("{ .reg .u64 t; cvta.to.shared.u64 t, %1; cvt.u32.u64 %0, t; }" : "=r"(a) : "l"(p));
    return a;
}
__device__ __forceinline__ void ldm_x4(uint32_t r[4], uint32_t addr) {
    asm volatile("ldmatrix.sync.aligned.m8n8.x4.shared.b16 {%0,%1,%2,%3}, [%4];"
        : "=r"(r[0]), "=r"(r[1]), "=r"(r[2]), "=r"(r[3]) : "r"(addr));
}
__device__ __forceinline__ void mma_f16(float c[4], const uint32_t a[4], const uint32_t b[2]) {
    asm volatile("mma.sync.aligned.m16n8k16.row.col.f32.f16.f16.f32 "
        "{%0,%1,%2,%3}, {%4,%5,%6,%7}, {%8,%9}, {%0,%1,%2,%3};"
        : "+f"(c[0]), "+f"(c[1]), "+f"(c[2]), "+f"(c[3])
        : "r"(a[0]), "r"(a[1]), "r"(a[2]), "r"(a[3]), "r"(b[0]), "r"(b[1]));
}
__device__ __forceinline__ void cpa16(uint32_t s, const void* g) {
    asm volatile("cp.async.cg.shared.global [%0], [%1], 16;"
        :: "r"(s), "l"(__cvta_generic_to_global(g)));
}
#define CP_COMMIT() asm volatile("cp.async.commit_group;" ::: "memory")
#define CP_WAIT0() asm volatile("cp.async.wait_group 0;" ::: "memory")
#define CP_WAIT1() asm volatile("cp.async.wait_group 1;" ::: "memory")

// ---------------- device scratch ----------------
__device__ float g_T[128 * 128];
__device__ float g_WkT[NC * NC];
__device__ float g_RK[128 * NC];
__device__ float g_PK[128 * NC];
__device__ float g_spart[(size_t)NB * 128 * 8192];
__device__ float g_S[NB * 8192];
__device__ float g_M[NB * NC * NC];          // transposed [co][ci]
__device__ float g_biasq[NB * NC];
__device__ float g_RQ[NB * 128 * NC];
__device__ float g_PQ[NB * 128 * NC];
__device__ __align__(16) __half g_Bw[2][256][264];      // Wk, Wv fp16 [co][ci]
__device__ __align__(16) __half g_Bm[NB][256][264];     // M fp16 [co][ci]
__device__ __align__(16) __half g_A[(size_t)NB * 128 * 32768];  // fp16 A tiles [tile][cig][tok][8]

// t1 smem (bytes): A@0 67584 | B@67584 (K rows 0-63, V rows 64-127) | KT@135168 | VT@152576 | SC@169984
#define T1_B   67584
#define KT_OFF 135168
#define VT_OFF 152576
#define SC_OFF 169984
#define T1_TOT 178176
// t3 smem: A@0 | B0@67584 | B1@135168 | mus@202752 | rss@203264
#define T3_B0  67584
#define T3_B1  135168
#define T3_MU  202752
#define T3_RS  203264
#define T3_TOT 203776

// ---------------- preps ----------------
__global__ void prep0a_kernel(const float* __restrict__ Wk) {
    int idx = blockIdx.x * 256 + threadIdx.x;
    int co = idx >> 8, ci = idx & 255;
    g_WkT[ci * NC + co] = Wk[idx];
    if (idx < 128 * 128) {
        int p = idx >> 7, c = idx & 127, j = c >> 1;
        float dimt = powf(10000.0f, (float)j * (1.0f / 64.0f));
        float t = (float)(p + 1) * (6.283185307179586f / (128.0f + 1e-6f)) / dimt;
        g_T[idx] = (c & 1) ? cosf(t) : sinf(t);
    }
}

__global__ void prep0b_kernel(const float* __restrict__ Wk, const float* __restrict__ Wv) {
    int idx = blockIdx.x * 256 + threadIdx.x;
    int co = idx >> 8, ci = idx & 255;
    g_Bw[0][co][ci] = __float2half_rn(Wk[idx]);
    g_Bw[1][co][ci] = __float2half_rn(Wv[idx]);
}

__global__ void prep1_kernel() {
    int table = blockIdx.x >> 3, chunk = blockIdx.x & 7;
    int n = chunk * 32 + (threadIdx.x & 31);
    int yg = threadIdx.x >> 5;
    float acc[16];
#pragma unroll
    for (int i = 0; i < 16; i++) acc[i] = 0.f;
    const float* W = g_WkT + (table ? 128 * NC : 0);
#pragma unroll 4
    for (int c = 0; c < 128; c++) {
        float w = W[c * NC + n];
#pragma unroll
        for (int yy = 0; yy < 16; yy++) acc[yy] += g_T[(yg * 16 + yy) * 128 + c] * w;
    }
    float* dst = table ? g_PK : g_RK;
#pragma unroll
    for (int yy = 0; yy < 16; yy++) dst[(yg * 16 + yy) * NC + n] = acc[yy];
}

// x[ci][tok] -> A[tok 128][ci 256 pad 264] fp16 (512 threads) + global A cache
__device__ __forceinline__ void load_x_tile_store(char* smem, const float* __restrict__ xb,
                                                  __half* __restrict__ gA, int tid) {
    int tok = tid & 127, cig = tid >> 7;
#pragma unroll 1
    for (int p = 0; p < 8; p++) {
        int ci0 = (cig + p * 4) * 8;
        __half hv[8];
#pragma unroll
        for (int j = 0; j < 8; j++)
            hv[j] = __float2half_rn(xb[(size_t)(ci0 + j) * NTOK + tok]);
        *(uint4*)(smem + tok * 528 + ci0 * 2) = *(uint4*)hv;
        *(uint4*)(gA + (ci0 >> 3) * 1024 + tok * 8) = *(uint4*)hv;
    }
}

// ---------------- T1: fp16 K/V proj (m32n32 warps) + in-reg LN + fp16 scores ----------------
__global__ void __launch_bounds__(512, 1) t1_kernel(
    const float* __restrict__ x,
    const float* __restrict__ bk, const float* __restrict__ bv,
    const float* __restrict__ gK, const float* __restrict__ bKp,
    const float* __restrict__ gV, const float* __restrict__ bVp)
{
    extern __shared__ char smem[];
    const int tid = threadIdx.x, w = tid >> 5, lane = tid & 31;
    const int rb = blockIdx.x, b = blockIdx.y;
    const int n0 = rb * 128;
    uint32_t sb = s2u(smem);

    const int op = w >> 3, mt = (w >> 1) & 3, ch = w & 1;   // K/V, m32 tile, n32 chunk
    const uint32_t aH0 = sb + (mt * 32 + (lane & 15)) * 528 + ((lane & 16) ? 16 : 0);
    const int blrow = (lane & 7) + ((lane & 16) ? 8 : 0);
    const int blcol2 = (lane & 8) ? 16 : 0;
    const uint32_t bbase = sb + T1_B + (op * 64 + ch * 32 + blrow) * 528 + blcol2;

    // pre-issue stage 0 (K+V chunk nc=0)
    for (int i = tid; i < 2112; i += 512) {
        cpa16(sb + T1_B + i * 16, ((const uint4*)&g_Bw[0][0][0]) + i);
        cpa16(sb + T1_B + 33792 + i * 16, ((const uint4*)&g_Bw[1][0][0]) + i);
    }
    CP_COMMIT();
    load_x_tile_store(smem, x + ((size_t)b * NC) * NTOK + n0,
                      g_A + (size_t)(b * 128 + rb) * 32768, tid);

#pragma unroll 1
    for (int nc = 0; nc < 4; nc++) {
        CP_WAIT0();
        __syncthreads();

        float acc[2][4][4];
#pragma unroll
        for (int t = 0; t < 2; t++)
#pragma unroll
            for (int f = 0; f < 4; f++)
#pragma unroll
                for (int j = 0; j < 4; j++) acc[t][f][j] = 0.f;

#pragma unroll 4
        for (int k = 0; k < 16; k++) {
            uint32_t a0[4], a1[4];
            ldm_x4(a0, aH0 + k * 32);
            ldm_x4(a1, aH0 + 16 * 528 + k * 32);
#pragma unroll
            for (int q = 0; q < 2; q++) {
                uint32_t bb[4];
                ldm_x4(bb, bbase + q * 16 * 528 + k * 32);
                mma_f16(acc[0][q * 2], a0, bb);
                mma_f16(acc[0][q * 2 + 1], a0, bb + 2);
                mma_f16(acc[1][q * 2], a1, bb);
                mma_f16(acc[1][q * 2 + 1], a1, bb + 2);
            }
        }
        __syncthreads();   // all B reads done; buffer free for next stage

        if (nc < 3) {
            for (int i = tid; i < 2112; i += 512) {
                cpa16(sb + T1_B + i * 16, ((const uint4*)&g_Bw[0][(nc + 1) * 64][0]) + i);
                cpa16(sb + T1_B + 33792 + i * 16, ((const uint4*)&g_Bw[1][(nc + 1) * 64][0]) + i);
            }
            CP_COMMIT();
        }

        // epilogue: +pos/bias in place -> per-row LN -> transposed fp16 store (head = nc*2+ch)
        {
            const int r0 = lane >> 2, cq = (lane & 3) * 2;
            const int head = nc * 2 + ch;
            if (op == 0) {
#pragma unroll
                for (int t = 0; t < 2; t++)
#pragma unroll
                    for (int f = 0; f < 4; f++) {
                        int co = nc * 64 + ch * 32 + f * 8 + cq;
                        float2 rk = *(const float2*)&g_RK[rb * NC + co];
                        float2 bkk = *(const float2*)&bk[co];
                        int rowA = mt * 32 + t * 16 + r0;
                        float2 pa = *(const float2*)&g_PK[rowA * NC + co];
                        float2 pb = *(const float2*)&g_PK[(rowA + 8) * NC + co];
                        acc[t][f][0] += rk.x + pa.x + bkk.x;
                        acc[t][f][1] += rk.y + pa.y + bkk.y;
                        acc[t][f][2] += rk.x + pb.x + bkk.x;
                        acc[t][f][3] += rk.y + pb.y + bkk.y;
                    }
            } else {
#pragma unroll
                for (int t = 0; t < 2; t++)
#pragma unroll
                    for (int f = 0; f < 4; f++) {
                        int co = nc * 64 + ch * 32 + f * 8 + cq;
                        float2 bv2 = *(const float2*)&bv[co];
                        acc[t][f][0] += bv2.x;
                        acc[t][f][1] += bv2.y;
                        acc[t][f][2] += bv2.x;
                        acc[t][f][3] += bv2.y;
                    }
            }
            const float* gg = op ? gV : gK;
            const float* be = op ? bVp : bKp;
            float gv[8], bb8[8];
#pragma unroll
            for (int f = 0; f < 4; f++)
#pragma unroll
                for (int j = 0; j < 2; j++) {
                    gv[f * 2 + j] = gg[head * 32 + f * 8 + cq + j];
                    bb8[f * 2 + j] = be[head * 32 + f * 8 + cq + j];
                }
            uint32_t base = sb + (op ? VT_OFF : KT_OFF);
#pragma unroll
            for (int t = 0; t < 2; t++)
#pragma unroll
                for (int rh = 0; rh < 2; rh++) {
                    int row = mt * 32 + t * 16 + rh * 8 + r0;
                    float s = 0.f, q2 = 0.f;
#pragma unroll
                    for (int f = 0; f < 4; f++)
#pragma unroll
                        for (int j = 0; j < 2; j++) {
                            float a = acc[t][f][rh * 2 + j];
                            s += a; q2 += a * a;
                        }
#pragma unroll
                    for (int off = 1; off < 4; off <<= 1) {
                        s += __shfl_xor_sync(0xffffffffu, s, off);
                        q2 += __shfl_xor_sync(0xffffffffu, q2, off);
                    }
                    float mu = s * (1.f / 32.f);
                    float rs = rsqrtf(q2 * (1.f / 32.f) - mu * mu + 1e-5f);
#pragma unroll
                    for (int f = 0; f < 4; f++)
#pragma unroll
                        for (int j = 0; j < 2; j++) {
                            int d = ch * 32 + f * 8 + cq + j;
                            __half h = __float2half_rn(
                                (acc[t][f][rh * 2 + j] - mu) * rs * gv[f * 2 + j] + bb8[f * 2 + j]);
                            asm volatile("st.shared.u16 [%0], %1;"
                                :: "r"(base + (uint32_t)d * 272 + row * 2), "h"(*(unsigned short*)&h));
                        }
                }
        }
        __syncthreads();

        // scores (16 warps, token-split, combined via smem scratch)
        {
            const int khalf = w >> 3, hl = (w >> 2) & 1, dt = (w >> 1) & 1, et = w & 1;
            const uint32_t aB = sb + KT_OFF + (hl * 32 + dt * 16 + (lane & 15)) * 272
                              + khalf * 128 + ((lane & 16) ? 16 : 0);
            const uint32_t bB = sb + VT_OFF + (hl * 32 + et * 16 + blrow) * 272
                              + khalf * 128 + blcol2;
            float sc[2][4];
#pragma unroll
            for (int q = 0; q < 2; q++)
#pragma unroll
                for (int j = 0; j < 4; j++) sc[q][j] = 0.f;
#pragma unroll
            for (int k = 0; k < 4; k++) {
                uint32_t a[4], bb[4];
                ldm_x4(a, aB + k * 32);
                ldm_x4(bb, bB + k * 32);
                mma_f16(sc[0], a, bb);
                mma_f16(sc[1], a, bb + 2);
            }
            float* scratch = (float*)(smem + SC_OFF);   // [2 heads][1024]
            int d0 = dt * 16 + (lane >> 2);
            if (khalf == 1) {
#pragma unroll
                for (int q = 0; q < 2; q++) {
                    int e0 = et * 16 + q * 8 + (lane & 3) * 2;
                    scratch[hl * 1024 + d0 * 32 + e0] = sc[q][0];
                    scratch[hl * 1024 + d0 * 32 + e0 + 1] = sc[q][1];
                    scratch[hl * 1024 + (d0 + 8) * 32 + e0] = sc[q][2];
                    scratch[hl * 1024 + (d0 + 8) * 32 + e0 + 1] = sc[q][3];
                }
            }
            __syncthreads();
            if (khalf == 0) {
                float* dst = g_spart + ((size_t)(b * 128 + rb)) * 8192 + (nc * 2 + hl) * 1024;
#pragma unroll
                for (int q = 0; q < 2; q++) {
                    int e0 = et * 16 + q * 8 + (lane & 3) * 2;
                    dst[d0 * 32 + e0] = sc[q][0] + scratch[hl * 1024 + d0 * 32 + e0];
                    dst[d0 * 32 + e0 + 1] = sc[q][1] + scratch[hl * 1024 + d0 * 32 + e0 + 1];
                    dst[(d0 + 8) * 32 + e0] = sc[q][2] + scratch[hl * 1024 + (d0 + 8) * 32 + e0];
                    dst[(d0 + 8) * 32 + e0 + 1] = sc[q][3] + scratch[hl * 1024 + (d0 + 8) * 32 + e0 + 1];
                }
            }
        }
    }
}

// ---------------- k2 chain ----------------
__global__ void k2_reduce() {
    int b = blockIdx.x >> 5, seg = blockIdx.x & 31;
    int base = seg * 256 + threadIdx.x;
    float s = 0.f;
#pragma unroll 8
    for (int rb = 0; rb < 128; rb++) s += g_spart[((size_t)(b * 128 + rb)) * 8192 + base];
    g_S[b * 8192 + base] = s * (1.0f / 16384.0f);
}

__global__ void k2b_buildM(const float* __restrict__ Wq, const float* __restrict__ bq) {
    __shared__ float Wqs[256 * 33];
    int chunk = blockIdx.x, b = blockIdx.y;
    int co = threadIdx.x, h = co >> 5, e = co & 31;
    for (int idx = threadIdx.x; idx < 8192; idx += 256) {
        int row = idx >> 5, cil = idx & 31;
        Wqs[row * 33 + cil] = Wq[row * NC + chunk * 32 + cil];
    }
    float Scol[32];
#pragma unroll
    for (int d = 0; d < 32; d++) Scol[d] = g_S[b * 8192 + h * 1024 + d * 32 + e];
    __syncthreads();
    for (int cil = 0; cil < 32; cil++) {
        float m = 0.f;
#pragma unroll
        for (int d = 0; d < 32; d++) m += Wqs[(h * 32 + d) * 33 + cil] * Scol[d];
        g_M[(size_t)b * 65536 + (size_t)co * NC + chunk * 32 + cil] = m;
        g_Bm[b][co][chunk * 32 + cil] = __float2half_rn(m);
    }
    if (chunk == 0) {
        float bb = 0.f;
#pragma unroll
        for (int d = 0; d < 32; d++) bb += bq[h * 32 + d] * Scol[d];
        g_biasq[b * NC + co] = bb;
    }
}

// grid (16, 8): 8 p-values per block; M read once per block
__global__ void k2c_rqpq() {
    __shared__ float Ts[8][128];
    int pg = blockIdx.x, b = blockIdx.y;
    int co = threadIdx.x;
    for (int i = threadIdx.x; i < 1024; i += 256)
        Ts[i >> 7][i & 127] = g_T[(pg * 8 + (i >> 7)) * 128 + (i & 127)];
    __syncthreads();
    const float4* Mr = (const float4*)(g_M + (size_t)b * 65536 + (size_t)co * NC);
    float aR[8], aP[8];
#pragma unroll
    for (int p = 0; p < 8; p++) { aR[p] = 0.f; aP[p] = 0.f; }
#pragma unroll 4
    for (int c4 = 0; c4 < 32; c4++) {
        float4 m0 = Mr[c4], m1 = Mr[32 + c4];
        float mm0[4] = {m0.x, m0.y, m0.z, m0.w};
        float mm1[4] = {m1.x, m1.y, m1.z, m1.w};
#pragma unroll
        for (int j = 0; j < 4; j++) {
            int c = c4 * 4 + j;
#pragma unroll
            for (int p = 0; p < 8; p++) {
                float tv = Ts[p][c];
                aR[p] += tv * mm0[j];
                aP[p] += tv * mm1[j];
            }
        }
    }
#pragma unroll
    for (int p = 0; p < 8; p++) {
        g_RQ[(b * 128 + pg * 8 + p) * NC + co] = aR[p];
        g_PQ[(b * 128 + pg * 8 + p) * NC + co] = aP[p];
    }
}

// ---------------- T3: fp16 out GEMM (m32n32 warps, 2 double-buffered stages) ----------------
__global__ void __launch_bounds__(512, 1) t3_kernel(
    const float* __restrict__ g_ln, const float* __restrict__ b_ln,
    float* __restrict__ out)
{
    extern __shared__ char smem[];
    const int tid = threadIdx.x, w = tid >> 5, lane = tid & 31;
    const int rb = blockIdx.x, b = blockIdx.y;
    const int n0 = rb * 128;
    uint32_t sb = s2u(smem);

    const int mt = w >> 2, ch = w & 3;      // m32 tile, n32 chunk within 128-co stage
    const uint32_t aH0 = sb + (mt * 32 + (lane & 15)) * 528 + ((lane & 16) ? 16 : 0);
    const int blrow = (lane & 7) + ((lane & 16) ? 8 : 0);
    const int blcol2 = (lane & 8) ? 16 : 0;

    // B0, then A (from fp16 cache), then B1 — three async groups
    for (int i = tid; i < 4224; i += 512)
        cpa16(sb + T3_B0 + i * 16, ((const uint4*)&g_Bm[b][0][0]) + i);
    CP_COMMIT();
    {
        const char* gA = (const char*)(g_A + (size_t)(b * 128 + rb) * 32768);
        for (int i = tid; i < 4096; i += 512)
            cpa16(sb + (uint32_t)(i & 127) * 528 + (uint32_t)(i >> 7) * 16, gA + (size_t)i * 16);
    }
    CP_COMMIT();
    for (int i = tid; i < 4224; i += 512)
        cpa16(sb + T3_B1 + i * 16, ((const uint4*)&g_Bm[b][128][0]) + i);
    CP_COMMIT();

    float acc[2][2][4][4];
#pragma unroll 1
    for (int s = 0; s < 2; s++) {
        if (s == 0) CP_WAIT1(); else CP_WAIT0();
        __syncthreads();
#pragma unroll
        for (int t = 0; t < 2; t++)
#pragma unroll
            for (int f = 0; f < 4; f++)
#pragma unroll
                for (int j = 0; j < 4; j++) acc[s][t][f][j] = 0.f;

        const uint32_t bbase = sb + (s ? T3_B1 : T3_B0) + (ch * 32 + blrow) * 528 + blcol2;
#pragma unroll 4
        for (int k = 0; k < 16; k++) {
            uint32_t a0[4], a1[4];
            ldm_x4(a0, aH0 + k * 32);
            ldm_x4(a1, aH0 + 16 * 528 + k * 32);
#pragma unroll
            for (int q = 0; q < 2; q++) {
                uint32_t bb[4];
                ldm_x4(bb, bbase + q * 16 * 528 + k * 32);
                mma_f16(acc[s][0][q * 2], a0, bb);
                mma_f16(acc[s][0][q * 2 + 1], a0, bb + 2);
                mma_f16(acc[s][1][q * 2], a1, bb);
                mma_f16(acc[s][1][q * 2 + 1], a1, bb + 2);
            }
        }
    }
    __syncthreads();

    float* stg = (float*)smem;          // [128][264] overlays A+B0
    float* mus = (float*)(smem + T3_MU);
    float* rss = (float*)(smem + T3_RS);
    {
        int r0 = lane >> 2, cq = (lane & 3) * 2;
#pragma unroll
        for (int s = 0; s < 2; s++)
#pragma unroll
            for (int t = 0; t < 2; t++)
#pragma unroll
                for (int rh = 0; rh < 2; rh++) {
                    int row = mt * 32 + t * 16 + rh * 8 + r0;
#pragma unroll
                    for (int f = 0; f < 4; f++) {
                        int co = s * 128 + ch * 32 + f * 8 + cq;
                        float2 rq = *(const float2*)&g_RQ[(b * 128 + rb) * NC + co];
                        float2 qb = *(const float2*)&g_biasq[b * NC + co];
                        float2 pq = *(const float2*)&g_PQ[(b * 128 + row) * NC + co];
                        stg[row * 264 + co] = 2.f * (acc[s][t][f][rh * 2] + rq.x + qb.x + pq.x);
                        stg[row * 264 + co + 1] = 2.f * (acc[s][t][f][rh * 2 + 1] + rq.y + qb.y + pq.y);
                    }
                }
    }
    __syncthreads();

    {   // LN stats: 4 threads per token
        int token = tid >> 2, q = tid & 3;
        float s = 0.f, s2 = 0.f;
#pragma unroll
        for (int jj = 0; jj < 16; jj++) {
            float4 v = *(const float4*)&stg[token * 264 + q * 64 + jj * 4];
            s += v.x + v.y + v.z + v.w;
            s2 += v.x * v.x + v.y * v.y + v.z * v.z + v.w * v.w;
        }
#pragma unroll
        for (int off = 1; off < 4; off <<= 1) {
            s += __shfl_xor_sync(0xffffffffu, s, off);
            s2 += __shfl_xor_sync(0xffffffffu, s2, off);
        }
        if (q == 0) {
            float mu = s * (1.f / 256.f);
            mus[token] = mu;
            rss[token] = rsqrtf(s2 * (1.f / 256.f) - mu * mu + 1e-5f);
        }
    }
    __syncthreads();

    {
        int t = tid & 127, cg = tid >> 7;
        float mu = mus[t], rs = rss[t];
        size_t obase = ((size_t)b * NC) * NTOK + n0 + t;
#pragma unroll 4
        for (int p = 0; p < 64; p++) {
            int co = cg * 64 + p;
            out[obase + (size_t)co * NTOK] = (stg[t * 264 + co] - mu) * rs * g_ln[co] + b_ln[co];
        }
    }
}

// ---------------- launch ----------------
extern "C" void kernel_launch(void* const* d_in, const int* in_sizes, int n_in,
                              void* d_out, int out_size) {
    const float* x    = (const float*)d_in[0];
    const float* Wq   = (const float*)d_in[1];
    const float* bq   = (const float*)d_in[2];
    const float* Wk   = (const float*)d_in[3];
    const float* bk   = (const float*)d_in[4];
    const float* Wv   = (const float*)d_in[5];
    const float* bv   = (const float*)d_in[6];
    const float* gK   = (const float*)d_in[7];
    const float* bK   = (const float*)d_in[8];
    const float* gV   = (const float*)d_in[9];
    const float* bV   = (const float*)d_in[10];
    const float* g_ln = (const float*)d_in[11];
    const float* b_ln = (const float*)d_in[12];
    float* out = (float*)d_out;

    cudaFuncSetAttribute(t1_kernel, cudaFuncAttributeMaxDynamicSharedMemorySize, T1_TOT);
    cudaFuncSetAttribute(t3_kernel, cudaFuncAttributeMaxDynamicSharedMemorySize, T3_TOT);

    prep0a_kernel<<<256, 256>>>(Wk);
    prep0b_kernel<<<256, 256>>>(Wk, Wv);
    prep1_kernel<<<16, 256>>>();
    t1_kernel<<<dim3(128, 8), 512, T1_TOT>>>(x, bk, bv, gK, bK, gV, bV);   // 4th launch -> profiled
    k2_reduce<<<256, 256>>>();
    k2b_buildM<<<dim3(8, 8), 256>>>(Wq, bq);
    k2c_rqpq<<<dim3(16, 8), 256>>>();
    t3_kernel<<<dim3(128, 8), 512, T3_TOT>>>(g_ln, b_ln, out);
}

// round 16
// speedup vs baseline: 1.3131x; 1.0310x over previous
#include <cuda_runtime.h>
#include <cuda_fp16.h>
#include <math.h>
#include <stdint.h>

#define NB 8
#define NC 256
#define NTOK 16384

__device__ __forceinline__ uint32_t s2u(const void* p) {
    uint32_t a;
    asm("{ .reg .u64 t; cvta.to.shared.u64 t, %1; cvt.u32.u64 %0, t; }" : "=r"(a) : "l"(p));
    return a;
}
__device__ __forceinline__ void ldm_x4(uint32_t r[4], uint32_t addr) {
    asm volatile("ldmatrix.sync.aligned.m8n8.x4.shared.b16 {%0,%1,%2,%3}, [%4];"
        : "=r"(r[0]), "=r"(r[1]), "=r"(r[2]), "=r"(r[3]) : "r"(addr));
}
__device__ __forceinline__ void mma_f16(float c[4], const uint32_t a[4], const uint32_t b[2]) {
    asm volatile("mma.sync.aligned.m16n8k16.row.col.f32.f16.f16.f32 "
        "{%0,%1,%2,%3}, {%4,%5,%6,%7}, {%8,%9}, {%0,%1,%2,%3};"
        : "+f"(c[0]), "+f"(c[1]), "+f"(c[2]), "+f"(c[3])
        : "r"(a[0]), "r"(a[1]), "r"(a[2]), "r"(a[3]), "r"(b[0]), "r"(b[1]));
}
__device__ __forceinline__ void cpa16(uint32_t s, const void* g) {
    asm volatile("cp.async.cg.shared.global [%0], [%1], 16;"
        :: "r"(s), "l"(__cvta_generic_to_global(g)));
}
#define CP_COMMIT() asm volatile("cp.async.commit_group;" ::: "memory")
#define CP_WAIT0() asm volatile("cp.async.wait_group 0;" ::: "memory")
#define CP_WAIT1() asm volatile("cp.async.wait_group 1;" ::: "memory")

// ---------------- device scratch ----------------
__device__ float g_T[128 * 128];
__device__ float g_WkT[NC * NC];
__device__ float g_RK[128 * NC];
__device__ float g_PK[128 * NC];
__device__ float g_spart[(size_t)NB * 128 * 8192];
__device__ float g_S[NB * 8192];
__device__ float g_M[NB * NC * NC];          // transposed [co][ci]
__device__ float g_biasq[NB * NC];
__device__ float g_RQ[NB * 128 * NC];        // holds RQ + biasq (folded in k2c)
__device__ float g_PQ[NB * 128 * NC];
__device__ __align__(16) __half g_Bw[2][256][264];      // Wk, Wv fp16 [co][ci]
__device__ __align__(16) __half g_Bm[NB][256][264];     // M fp16 [co][ci]
__device__ __align__(16) __half g_A[(size_t)NB * 128 * 32768];  // fp16 A tiles [tile][cig][tok][8]

// t1 smem (bytes)
#define T1_B   67584
#define KT_OFF 135168
#define VT_OFF 152576
#define SC_OFF 169984
#define T1_TOT 178176
// t3 smem: A@0 | B0@67584 | B1@135168 | red@202752 | mus@206848 | rss@207360 | lns@207872 | lnb@208896 | rqs@209920
#define T3_B0   67584
#define T3_B1   135168
#define RED_OFF 202752
#define MU_OFF  206848
#define RS_OFF  207360
#define LNS_OFF 207872
#define LNB_OFF 208896
#define RQS_OFF 209920
#define T3_TOT  210944

// ---------------- preps ----------------
__global__ void prep0a_kernel(const float* __restrict__ Wk) {
    int idx = blockIdx.x * 256 + threadIdx.x;
    int co = idx >> 8, ci = idx & 255;
    g_WkT[ci * NC + co] = Wk[idx];
    if (idx < 128 * 128) {
        int p = idx >> 7, c = idx & 127, j = c >> 1;
        float dimt = powf(10000.0f, (float)j * (1.0f / 64.0f));
        float t = (float)(p + 1) * (6.283185307179586f / (128.0f + 1e-6f)) / dimt;
        g_T[idx] = (c & 1) ? cosf(t) : sinf(t);
    }
}

__global__ void prep0b_kernel(const float* __restrict__ Wk, const float* __restrict__ Wv) {
    int idx = blockIdx.x * 256 + threadIdx.x;
    int co = idx >> 8, ci = idx & 255;
    g_Bw[0][co][ci] = __float2half_rn(Wk[idx]);
    g_Bw[1][co][ci] = __float2half_rn(Wv[idx]);
}

__global__ void prep1_kernel() {
    int table = blockIdx.x >> 3, chunk = blockIdx.x & 7;
    int n = chunk * 32 + (threadIdx.x & 31);
    int yg = threadIdx.x >> 5;
    float acc[16];
#pragma unroll
    for (int i = 0; i < 16; i++) acc[i] = 0.f;
    const float* W = g_WkT + (table ? 128 * NC : 0);
#pragma unroll 4
    for (int c = 0; c < 128; c++) {
        float w = W[c * NC + n];
#pragma unroll
        for (int yy = 0; yy < 16; yy++) acc[yy] += g_T[(yg * 16 + yy) * 128 + c] * w;
    }
    float* dst = table ? g_PK : g_RK;
#pragma unroll
    for (int yy = 0; yy < 16; yy++) dst[(yg * 16 + yy) * NC + n] = acc[yy];
}

// x[ci][tok] -> A[tok 128][ci 256 pad 264] fp16 (512 threads) + global A cache
__device__ __forceinline__ void load_x_tile_store(char* smem, const float* __restrict__ xb,
                                                  __half* __restrict__ gA, int tid) {
    int tok = tid & 127, cig = tid >> 7;
#pragma unroll 1
    for (int p = 0; p < 8; p++) {
        int ci0 = (cig + p * 4) * 8;
        __half hv[8];
#pragma unroll
        for (int j = 0; j < 8; j++)
            hv[j] = __float2half_rn(xb[(size_t)(ci0 + j) * NTOK + tok]);
        *(uint4*)(smem + tok * 528 + ci0 * 2) = *(uint4*)hv;
        *(uint4*)(gA + (ci0 >> 3) * 1024 + tok * 8) = *(uint4*)hv;
    }
}

// ---------------- T1: fp16 K/V proj (m32n32 warps) + in-reg LN + fp16 scores ----------------
__global__ void __launch_bounds__(512, 1) t1_kernel(
    const float* __restrict__ x,
    const float* __restrict__ bk, const float* __restrict__ bv,
    const float* __restrict__ gK, const float* __restrict__ bKp,
    const float* __restrict__ gV, const float* __restrict__ bVp)
{
    extern __shared__ char smem[];
    const int tid = threadIdx.x, w = tid >> 5, lane = tid & 31;
    const int rb = blockIdx.x, b = blockIdx.y;
    const int n0 = rb * 128;
    uint32_t sb = s2u(smem);

    const int op = w >> 3, mt = (w >> 1) & 3, ch = w & 1;   // K/V, m32 tile, n32 chunk
    const uint32_t aH0 = sb + (mt * 32 + (lane & 15)) * 528 + ((lane & 16) ? 16 : 0);
    const int blrow = (lane & 7) + ((lane & 16) ? 8 : 0);
    const int blcol2 = (lane & 8) ? 16 : 0;
    const uint32_t bbase = sb + T1_B + (op * 64 + ch * 32 + blrow) * 528 + blcol2;

    for (int i = tid; i < 2112; i += 512) {
        cpa16(sb + T1_B + i * 16, ((const uint4*)&g_Bw[0][0][0]) + i);
        cpa16(sb + T1_B + 33792 + i * 16, ((const uint4*)&g_Bw[1][0][0]) + i);
    }
    CP_COMMIT();
    load_x_tile_store(smem, x + ((size_t)b * NC) * NTOK + n0,
                      g_A + (size_t)(b * 128 + rb) * 32768, tid);

#pragma unroll 1
    for (int nc = 0; nc < 4; nc++) {
        CP_WAIT0();
        __syncthreads();

        float acc[2][4][4];
#pragma unroll
        for (int t = 0; t < 2; t++)
#pragma unroll
            for (int f = 0; f < 4; f++)
#pragma unroll
                for (int j = 0; j < 4; j++) acc[t][f][j] = 0.f;

#pragma unroll 4
        for (int k = 0; k < 16; k++) {
            uint32_t a0[4], a1[4];
            ldm_x4(a0, aH0 + k * 32);
            ldm_x4(a1, aH0 + 16 * 528 + k * 32);
#pragma unroll
            for (int q = 0; q < 2; q++) {
                uint32_t bb[4];
                ldm_x4(bb, bbase + q * 16 * 528 + k * 32);
                mma_f16(acc[0][q * 2], a0, bb);
                mma_f16(acc[0][q * 2 + 1], a0, bb + 2);
                mma_f16(acc[1][q * 2], a1, bb);
                mma_f16(acc[1][q * 2 + 1], a1, bb + 2);
            }
        }
        __syncthreads();

        if (nc < 3) {
            for (int i = tid; i < 2112; i += 512) {
                cpa16(sb + T1_B + i * 16, ((const uint4*)&g_Bw[0][(nc + 1) * 64][0]) + i);
                cpa16(sb + T1_B + 33792 + i * 16, ((const uint4*)&g_Bw[1][(nc + 1) * 64][0]) + i);
            }
            CP_COMMIT();
        }

        // epilogue: +pos/bias in place -> per-row LN -> transposed fp16 store (head = nc*2+ch)
        {
            const int r0 = lane >> 2, cq = (lane & 3) * 2;
            const int head = nc * 2 + ch;
            if (op == 0) {
#pragma unroll
                for (int t = 0; t < 2; t++)
#pragma unroll
                    for (int f = 0; f < 4; f++) {
                        int co = nc * 64 + ch * 32 + f * 8 + cq;
                        float2 rk = *(const float2*)&g_RK[rb * NC + co];
                        float2 bkk = *(const float2*)&bk[co];
                        int rowA = mt * 32 + t * 16 + r0;
                        float2 pa = *(const float2*)&g_PK[rowA * NC + co];
                        float2 pb = *(const float2*)&g_PK[(rowA + 8) * NC + co];
                        acc[t][f][0] += rk.x + pa.x + bkk.x;
                        acc[t][f][1] += rk.y + pa.y + bkk.y;
                        acc[t][f][2] += rk.x + pb.x + bkk.x;
                        acc[t][f][3] += rk.y + pb.y + bkk.y;
                    }
            } else {
#pragma unroll
                for (int t = 0; t < 2; t++)
#pragma unroll
                    for (int f = 0; f < 4; f++) {
                        int co = nc * 64 + ch * 32 + f * 8 + cq;
                        float2 bv2 = *(const float2*)&bv[co];
                        acc[t][f][0] += bv2.x;
                        acc[t][f][1] += bv2.y;
                        acc[t][f][2] += bv2.x;
                        acc[t][f][3] += bv2.y;
                    }
            }
            const float* gg = op ? gV : gK;
            const float* be = op ? bVp : bKp;
            float gv[8], bb8[8];
#pragma unroll
            for (int f = 0; f < 4; f++)
#pragma unroll
                for (int j = 0; j < 2; j++) {
                    gv[f * 2 + j] = gg[head * 32 + f * 8 + cq + j];
                    bb8[f * 2 + j] = be[head * 32 + f * 8 + cq + j];
                }
            uint32_t base = sb + (op ? VT_OFF : KT_OFF);
#pragma unroll
            for (int t = 0; t < 2; t++)
#pragma unroll
                for (int rh = 0; rh < 2; rh++) {
                    int row = mt * 32 + t * 16 + rh * 8 + r0;
                    float s = 0.f, q2 = 0.f;
#pragma unroll
                    for (int f = 0; f < 4; f++)
#pragma unroll
                        for (int j = 0; j < 2; j++) {
                            float a = acc[t][f][rh * 2 + j];
                            s += a; q2 += a * a;
                        }
#pragma unroll
                    for (int off = 1; off < 4; off <<= 1) {
                        s += __shfl_xor_sync(0xffffffffu, s, off);
                        q2 += __shfl_xor_sync(0xffffffffu, q2, off);
                    }
                    float mu = s * (1.f / 32.f);
                    float rs = rsqrtf(q2 * (1.f / 32.f) - mu * mu + 1e-5f);
#pragma unroll
                    for (int f = 0; f < 4; f++)
#pragma unroll
                        for (int j = 0; j < 2; j++) {
                            int d = ch * 32 + f * 8 + cq + j;
                            __half h = __float2half_rn(
                                (acc[t][f][rh * 2 + j] - mu) * rs * gv[f * 2 + j] + bb8[f * 2 + j]);
                            asm volatile("st.shared.u16 [%0], %1;"
                                :: "r"(base + (uint32_t)d * 272 + row * 2), "h"(*(unsigned short*)&h));
                        }
                }
        }
        __syncthreads();

        // scores (16 warps, token-split, combined via smem scratch)
        {
            const int khalf = w >> 3, hl = (w >> 2) & 1, dt = (w >> 1) & 1, et = w & 1;
            const uint32_t aB = sb + KT_OFF + (hl * 32 + dt * 16 + (lane & 15)) * 272
                              + khalf * 128 + ((lane & 16) ? 16 : 0);
            const uint32_t bB = sb + VT_OFF + (hl * 32 + et * 16 + blrow) * 272
                              + khalf * 128 + blcol2;
            float sc[2][4];
#pragma unroll
            for (int q = 0; q < 2; q++)
#pragma unroll
                for (int j = 0; j < 4; j++) sc[q][j] = 0.f;
#pragma unroll
            for (int k = 0; k < 4; k++) {
                uint32_t a[4], bb[4];
                ldm_x4(a, aB + k * 32);
                ldm_x4(bb, bB + k * 32);
                mma_f16(sc[0], a, bb);
                mma_f16(sc[1], a, bb + 2);
            }
            float* scratch = (float*)(smem + SC_OFF);   // [2 heads][1024]
            int d0 = dt * 16 + (lane >> 2);
            if (khalf == 1) {
#pragma unroll
                for (int q = 0; q < 2; q++) {
                    int e0 = et * 16 + q * 8 + (lane & 3) * 2;
                    scratch[hl * 1024 + d0 * 32 + e0] = sc[q][0];
                    scratch[hl * 1024 + d0 * 32 + e0 + 1] = sc[q][1];
                    scratch[hl * 1024 + (d0 + 8) * 32 + e0] = sc[q][2];
                    scratch[hl * 1024 + (d0 + 8) * 32 + e0 + 1] = sc[q][3];
                }
            }
            __syncthreads();
            if (khalf == 0) {
                float* dst = g_spart + ((size_t)(b * 128 + rb)) * 8192 + (nc * 2 + hl) * 1024;
#pragma unroll
                for (int q = 0; q < 2; q++) {
                    int e0 = et * 16 + q * 8 + (lane & 3) * 2;
                    dst[d0 * 32 + e0] = sc[q][0] + scratch[hl * 1024 + d0 * 32 + e0];
                    dst[d0 * 32 + e0 + 1] = sc[q][1] + scratch[hl * 1024 + d0 * 32 + e0 + 1];
                    dst[(d0 + 8) * 32 + e0] = sc[q][2] + scratch[hl * 1024 + (d0 + 8) * 32 + e0];
                    dst[(d0 + 8) * 32 + e0 + 1] = sc[q][3] + scratch[hl * 1024 + (d0 + 8) * 32 + e0 + 1];
                }
            }
        }
    }
}

// ---------------- k2 chain ----------------
__global__ void k2_reduce() {
    int b = blockIdx.x >> 5, seg = blockIdx.x & 31;
    int base = seg * 256 + threadIdx.x;
    float s = 0.f;
#pragma unroll 8
    for (int rb = 0; rb < 128; rb++) s += g_spart[((size_t)(b * 128 + rb)) * 8192 + base];
    g_S[b * 8192 + base] = s * (1.0f / 16384.0f);
}

__global__ void k2b_buildM(const float* __restrict__ Wq, const float* __restrict__ bq) {
    __shared__ float Wqs[256 * 33];
    int chunk = blockIdx.x, b = blockIdx.y;
    int co = threadIdx.x, h = co >> 5, e = co & 31;
    for (int idx = threadIdx.x; idx < 8192; idx += 256) {
        int row = idx >> 5, cil = idx & 31;
        Wqs[row * 33 + cil] = Wq[row * NC + chunk * 32 + cil];
    }
    float Scol[32];
#pragma unroll
    for (int d = 0; d < 32; d++) Scol[d] = g_S[b * 8192 + h * 1024 + d * 32 + e];
    __syncthreads();
    for (int cil = 0; cil < 32; cil++) {
        float m = 0.f;
#pragma unroll
        for (int d = 0; d < 32; d++) m += Wqs[(h * 32 + d) * 33 + cil] * Scol[d];
        g_M[(size_t)b * 65536 + (size_t)co * NC + chunk * 32 + cil] = m;
        g_Bm[b][co][chunk * 32 + cil] = __float2half_rn(m);
    }
    if (chunk == 0) {
        float bb = 0.f;
#pragma unroll
        for (int d = 0; d < 32; d++) bb += bq[h * 32 + d] * Scol[d];
        g_biasq[b * NC + co] = bb;
    }
}

// grid (16, 8): 8 p-values per block; RQ gets biasq folded in
__global__ void k2c_rqpq() {
    __shared__ float Ts[8][128];
    int pg = blockIdx.x, b = blockIdx.y;
    int co = threadIdx.x;
    for (int i = threadIdx.x; i < 1024; i += 256)
        Ts[i >> 7][i & 127] = g_T[(pg * 8 + (i >> 7)) * 128 + (i & 127)];
    __syncthreads();
    const float4* Mr = (const float4*)(g_M + (size_t)b * 65536 + (size_t)co * NC);
    float bqv = g_biasq[b * NC + co];
    float aR[8], aP[8];
#pragma unroll
    for (int p = 0; p < 8; p++) { aR[p] = 0.f; aP[p] = 0.f; }
#pragma unroll 4
    for (int c4 = 0; c4 < 32; c4++) {
        float4 m0 = Mr[c4], m1 = Mr[32 + c4];
        float mm0[4] = {m0.x, m0.y, m0.z, m0.w};
        float mm1[4] = {m1.x, m1.y, m1.z, m1.w};
#pragma unroll
        for (int j = 0; j < 4; j++) {
            int c = c4 * 4 + j;
#pragma unroll
            for (int p = 0; p < 8; p++) {
                float tv = Ts[p][c];
                aR[p] += tv * mm0[j];
                aP[p] += tv * mm1[j];
            }
        }
    }
#pragma unroll
    for (int p = 0; p < 8; p++) {
        g_RQ[(b * 128 + pg * 8 + p) * NC + co] = aR[p] + bqv;
        g_PQ[(b * 128 + pg * 8 + p) * NC + co] = aP[p];
    }
}

// ---------------- T3: fp16 out GEMM, register epilogue + LN, no staging ----------------
__global__ void __launch_bounds__(512, 1) t3_kernel(
    const float* __restrict__ g_ln, const float* __restrict__ b_ln,
    float* __restrict__ out)
{
    extern __shared__ char smem[];
    const int tid = threadIdx.x, w = tid >> 5, lane = tid & 31;
    const int rb = blockIdx.x, b = blockIdx.y;
    const int n0 = rb * 128;
    uint32_t sb = s2u(smem);

    float* red = (float*)(smem + RED_OFF);   // [128][8]
    float* mus = (float*)(smem + MU_OFF);
    float* rss = (float*)(smem + RS_OFF);
    float* lns = (float*)(smem + LNS_OFF);
    float* lnb = (float*)(smem + LNB_OFF);
    float* rqs = (float*)(smem + RQS_OFF);

    const int mt = w >> 2, ch = w & 3;
    const uint32_t aH0 = sb + (mt * 32 + (lane & 15)) * 528 + ((lane & 16) ? 16 : 0);
    const int blrow = (lane & 7) + ((lane & 16) ? 8 : 0);
    const int blcol2 = (lane & 8) ? 16 : 0;

    for (int i = tid; i < 4224; i += 512)
        cpa16(sb + T3_B0 + i * 16, ((const uint4*)&g_Bm[b][0][0]) + i);
    CP_COMMIT();
    {
        const char* gA = (const char*)(g_A + (size_t)(b * 128 + rb) * 32768);
        for (int i = tid; i < 4096; i += 512)
            cpa16(sb + (uint32_t)(i & 127) * 528 + (uint32_t)(i >> 7) * 16, gA + (size_t)i * 16);
    }
    CP_COMMIT();
    for (int i = tid; i < 4224; i += 512)
        cpa16(sb + T3_B1 + i * 16, ((const uint4*)&g_Bm[b][128][0]) + i);
    CP_COMMIT();

    if (tid < 256) {
        lns[tid] = g_ln[tid];
        lnb[tid] = b_ln[tid];
        rqs[tid] = g_RQ[(b * 128 + rb) * NC + tid];   // RQ + biasq (folded)
    }

    float acc[2][2][4][4];
#pragma unroll 1
    for (int s = 0; s < 2; s++) {
        if (s == 0) CP_WAIT1(); else CP_WAIT0();
        __syncthreads();
#pragma unroll
        for (int t = 0; t < 2; t++)
#pragma unroll
            for (int f = 0; f < 4; f++)
#pragma unroll
                for (int j = 0; j < 4; j++) acc[s][t][f][j] = 0.f;

        const uint32_t bbase = sb + (s ? T3_B1 : T3_B0) + (ch * 32 + blrow) * 528 + blcol2;
#pragma unroll 4
        for (int k = 0; k < 16; k++) {
            uint32_t a0[4], a1[4];
            ldm_x4(a0, aH0 + k * 32);
            ldm_x4(a1, aH0 + 16 * 528 + k * 32);
#pragma unroll
            for (int q = 0; q < 2; q++) {
                uint32_t bb[4];
                ldm_x4(bb, bbase + q * 16 * 528 + k * 32);
                mma_f16(acc[s][0][q * 2], a0, bb);
                mma_f16(acc[s][0][q * 2 + 1], a0, bb + 2);
                mma_f16(acc[s][1][q * 2], a1, bb);
                mma_f16(acc[s][1][q * 2 + 1], a1, bb + 2);
            }
        }
    }

    // register epilogue: +RQ~+PQ, x2, row partial sums -> red
    const int r0 = lane >> 2, cq = (lane & 3) * 2;
#pragma unroll
    for (int t = 0; t < 2; t++)
#pragma unroll
        for (int rh = 0; rh < 2; rh++) {
            int row = mt * 32 + t * 16 + rh * 8 + r0;
            float s = 0.f, s2 = 0.f;
#pragma unroll
            for (int ss = 0; ss < 2; ss++)
#pragma unroll
                for (int f = 0; f < 4; f++) {
                    int co = ss * 128 + ch * 32 + f * 8 + cq;
                    float2 pq = *(const float2*)&g_PQ[(b * 128 + row) * NC + co];
                    float v0 = 2.f * (acc[ss][t][f][rh * 2] + rqs[co] + pq.x);
                    float v1 = 2.f * (acc[ss][t][f][rh * 2 + 1] + rqs[co + 1] + pq.y);
                    acc[ss][t][f][rh * 2] = v0;
                    acc[ss][t][f][rh * 2 + 1] = v1;
                    s += v0 + v1; s2 += v0 * v0 + v1 * v1;
                }
            s += __shfl_xor_sync(0xffffffffu, s, 1);
            s2 += __shfl_xor_sync(0xffffffffu, s2, 1);
            s += __shfl_xor_sync(0xffffffffu, s, 2);
            s2 += __shfl_xor_sync(0xffffffffu, s2, 2);
            if ((lane & 3) == 0) {
                red[row * 8 + ch * 2] = s;
                red[row * 8 + ch * 2 + 1] = s2;
            }
        }
    __syncthreads();
    if (tid < 128) {
        float s = red[tid * 8] + red[tid * 8 + 2] + red[tid * 8 + 4] + red[tid * 8 + 6];
        float s2 = red[tid * 8 + 1] + red[tid * 8 + 3] + red[tid * 8 + 5] + red[tid * 8 + 7];
        float mu = s * (1.f / 256.f);
        mus[tid] = mu;
        rss[tid] = rsqrtf(s2 * (1.f / 256.f) - mu * mu + 1e-5f);
    }
    __syncthreads();

    float mur[4], rsr[4];
#pragma unroll
    for (int t = 0; t < 2; t++)
#pragma unroll
        for (int rh = 0; rh < 2; rh++) {
            int row = mt * 32 + t * 16 + rh * 8 + r0;
            mur[t * 2 + rh] = mus[row];
            rsr[t * 2 + rh] = rss[row];
        }
#pragma unroll
    for (int ss = 0; ss < 2; ss++)
#pragma unroll
        for (int f = 0; f < 4; f++)
#pragma unroll
            for (int j = 0; j < 2; j++) {
                int co = ss * 128 + ch * 32 + f * 8 + cq + j;
                float g = lns[co], bb2 = lnb[co];
                float* ob = out + (size_t)(b * NC + co) * NTOK + n0;
#pragma unroll
                for (int t = 0; t < 2; t++)
#pragma unroll
                    for (int rh = 0; rh < 2; rh++) {
                        int row = mt * 32 + t * 16 + rh * 8 + r0;
                        ob[row] = (acc[ss][t][f][rh * 2 + j] - mur[t * 2 + rh]) * rsr[t * 2 + rh] * g + bb2;
                    }
            }
}

// ---------------- launch ----------------
extern "C" void kernel_launch(void* const* d_in, const int* in_sizes, int n_in,
                              void* d_out, int out_size) {
    const float* x    = (const float*)d_in[0];
    const float* Wq   = (const float*)d_in[1];
    const float* bq   = (const float*)d_in[2];
    const float* Wk   = (const float*)d_in[3];
    const float* bk   = (const float*)d_in[4];
    const float* Wv   = (const float*)d_in[5];
    const float* bv   = (const float*)d_in[6];
    const float* gK   = (const float*)d_in[7];
    const float* bK   = (const float*)d_in[8];
    const float* gV   = (const float*)d_in[9];
    const float* bV   = (const float*)d_in[10];
    const float* g_ln = (const float*)d_in[11];
    const float* b_ln = (const float*)d_in[12];
    float* out = (float*)d_out;

    cudaFuncSetAttribute(t1_kernel, cudaFuncAttributeMaxDynamicSharedMemorySize, T1_TOT);
    cudaFuncSetAttribute(t3_kernel, cudaFuncAttributeMaxDynamicSharedMemorySize, T3_TOT);

    prep0a_kernel<<<256, 256>>>(Wk);
    prep0b_kernel<<<256, 256>>>(Wk, Wv);
    prep1_kernel<<<16, 256>>>();
    t1_kernel<<<dim3(128, 8), 512, T1_TOT>>>(x, bk, bv, gK, bK, gV, bV);
    k2_reduce<<<256, 256>>>();
    k2b_buildM<<<dim3(8, 8), 256>>>(Wq, bq);
    k2c_rqpq<<<dim3(16, 8), 256>>>();
    t3_kernel<<<dim3(128, 8), 512, T3_TOT>>>(g_ln, b_ln, out);
}